// round 6
// baseline (speedup 1.0000x reference)
#include <cuda_runtime.h>
#include <math.h>

// Problem dims (fixed)
#define Bb 32
#define C 512
#define HW 1024          // 32*32 spatial
#define GROUPS 32
#define CPG 16           // channels per group
#define QKV_O 1536       // 3*C
#define SEG 32           // softmax segment length (last spatial axis j)

// -------- device scratch (alloc-free rule: __device__ globals) --------
__device__ float g_hin [Bb * C * HW];       // group-normed input  [B,C,HW]
__device__ float g_qkv [Bb * QKV_O * HW];   // qkv                 [B,3C,HW]
__device__ float g_attn[Bb * HW * HW];      // attention           [B,HW,HW]
__device__ float g_h   [Bb * C * HW];       // attn output         [B,C,HW]

// ======================= GroupNorm =======================
// grid = B*GROUPS blocks, 256 threads. group size = CPG*HW = 16384 floats.
__global__ void groupnorm_kernel(const float* __restrict__ x,
                                 const float* __restrict__ gamma,
                                 const float* __restrict__ beta,
                                 float* __restrict__ out)
{
    const int b = blockIdx.x / GROUPS;
    const int g = blockIdx.x % GROUPS;
    const long base = ((long)b * C + (long)g * CPG) * HW;
    const int GSZ = CPG * HW; // 16384
    const int tid = threadIdx.x;

    float sum = 0.f, sq = 0.f;
    for (int i = tid; i < GSZ; i += 256) {
        float v = x[base + i];
        sum += v; sq += v * v;
    }
    // block reduce
    __shared__ float s_sum[8], s_sq[8];
    for (int off = 16; off > 0; off >>= 1) {
        sum += __shfl_xor_sync(0xffffffff, sum, off);
        sq  += __shfl_xor_sync(0xffffffff, sq,  off);
    }
    if ((tid & 31) == 0) { s_sum[tid >> 5] = sum; s_sq[tid >> 5] = sq; }
    __syncthreads();
    if (tid < 8) { sum = s_sum[tid]; sq = s_sq[tid]; }
    else         { sum = 0.f; sq = 0.f; }
    if (tid < 32) {
        for (int off = 4; off > 0; off >>= 1) {
            sum += __shfl_xor_sync(0xffffffff, sum, off);
            sq  += __shfl_xor_sync(0xffffffff, sq,  off);
        }
        if (tid == 0) { s_sum[0] = sum; s_sq[0] = sq; }
    }
    __syncthreads();
    const float mean = s_sum[0] * (1.f / GSZ);
    const float var  = s_sq[0]  * (1.f / GSZ) - mean * mean;
    const float rstd = rsqrtf(var + 1e-5f);

    for (int i = tid; i < GSZ; i += 256) {
        int c = g * CPG + i / HW;
        float v = (x[base + i] - mean) * rstd;
        out[base + i] = v * gamma[c] + beta[c];
    }
}

// ======================= Generic batched SGEMM =======================
// C[m,n] = alpha * sum_k A(m,k)*B(k,n)  (+ bias[m]) (+ residual[m,n])
// TA: A stored [K,M] (lda=M stride over k). else [M,K] (lda=K).
// TB: B stored [N,K] (ldb=K stride over n). else [K,N] (ldb=N).
// ldc = N. Batch via z-dim with elem strides.
template<bool TA, bool TB>
__global__ void gemm64(const float* __restrict__ A, const float* __restrict__ B,
                       float* __restrict__ Cm,
                       int M, int N, int K, int lda, int ldb,
                       long strideA, long strideB, long strideC,
                       float alpha,
                       const float* __restrict__ bias,
                       const float* __restrict__ residual, long strideR)
{
    constexpr int BM = 64, BN = 64, BK = 16, PAD = 4;
    __shared__ float As[BK][BM + PAD];
    __shared__ float Bs[BK][BN + PAD];

    const int z = blockIdx.z;
    A += z * strideA;
    B += z * strideB;
    Cm += z * strideC;
    if (residual) residual += z * strideR;

    const int m0 = blockIdx.y * BM;
    const int n0 = blockIdx.x * BN;
    const int tid = threadIdx.x;      // 256 threads
    const int tx = tid & 15;          // 0..15
    const int ty = tid >> 4;          // 0..15

    float acc[4][4];
    #pragma unroll
    for (int i = 0; i < 4; i++)
        #pragma unroll
        for (int j = 0; j < 4; j++) acc[i][j] = 0.f;

    for (int k0 = 0; k0 < K; k0 += BK) {
        // ---- load A tile ----
        if (TA) {
            // A[K,M]: direct copy rows
            int kk = tid >> 4;             // 0..15
            int mq = (tid & 15) << 2;      // 0..60
            float4 v = *(const float4*)&A[(long)(k0 + kk) * lda + (m0 + mq)];
            *(float4*)&As[kk][mq] = v;
        } else {
            // A[M,K]: load row chunk, scatter-transpose
            int mm = tid >> 2;             // 0..63
            int kq = (tid & 3) << 2;       // 0..12
            float4 v = *(const float4*)&A[(long)(m0 + mm) * lda + (k0 + kq)];
            As[kq + 0][mm] = v.x;
            As[kq + 1][mm] = v.y;
            As[kq + 2][mm] = v.z;
            As[kq + 3][mm] = v.w;
        }
        // ---- load B tile ----
        if (TB) {
            // B[N,K]: load row chunk, scatter-transpose
            int nn = tid >> 2;
            int kq = (tid & 3) << 2;
            float4 v = *(const float4*)&B[(long)(n0 + nn) * ldb + (k0 + kq)];
            Bs[kq + 0][nn] = v.x;
            Bs[kq + 1][nn] = v.y;
            Bs[kq + 2][nn] = v.z;
            Bs[kq + 3][nn] = v.w;
        } else {
            // B[K,N]: direct copy
            int kk = tid >> 4;
            int nq = (tid & 15) << 2;
            float4 v = *(const float4*)&B[(long)(k0 + kk) * ldb + (n0 + nq)];
            *(float4*)&Bs[kk][nq] = v;
        }
        __syncthreads();

        #pragma unroll
        for (int kk = 0; kk < BK; kk++) {
            float a[4], bqv[4];
            #pragma unroll
            for (int i = 0; i < 4; i++) a[i]   = As[kk][ty * 4 + i];
            #pragma unroll
            for (int j = 0; j < 4; j++) bqv[j] = Bs[kk][tx * 4 + j];
            #pragma unroll
            for (int i = 0; i < 4; i++)
                #pragma unroll
                for (int j = 0; j < 4; j++)
                    acc[i][j] = fmaf(a[i], bqv[j], acc[i][j]);
        }
        __syncthreads();
    }

    #pragma unroll
    for (int i = 0; i < 4; i++) {
        int m = m0 + ty * 4 + i;
        float bv = bias ? bias[m] : 0.f;
        #pragma unroll
        for (int j = 0; j < 4; j++) {
            int n = n0 + tx * 4 + j;
            float v = alpha * acc[i][j] + bv;
            if (residual) v += residual[(long)m * N + n];
            Cm[(long)m * N + n] = v;
        }
    }
}

// ======================= Segmented softmax =======================
// Reference softmaxes over the LAST spatial axis j only (32 elements), i.e.
// attn[b,h,w,i,:] — in our [p, i*32+j] layout that is each contiguous
// 32-element chunk of a row. One warp per segment; 8 warps per block.
__global__ void softmax_seg_kernel(float* __restrict__ attn)
{
    const long seg = (long)blockIdx.x * 8 + (threadIdx.x >> 5);
    const int lane = threadIdx.x & 31;
    float* p = attn + seg * SEG;

    float v = p[lane];
    float mx = v;
    #pragma unroll
    for (int off = 16; off > 0; off >>= 1)
        mx = fmaxf(mx, __shfl_xor_sync(0xffffffff, mx, off));
    v = __expf(v - mx);
    float s = v;
    #pragma unroll
    for (int off = 16; off > 0; off >>= 1)
        s += __shfl_xor_sync(0xffffffff, s, off);
    p[lane] = v / s;
}

// ======================= launch =======================
extern "C" void kernel_launch(void* const* d_in, const int* in_sizes, int n_in,
                              void* d_out, int out_size)
{
    const float* x       = (const float*)d_in[0];
    const float* gamma   = (const float*)d_in[1];
    const float* beta    = (const float*)d_in[2];
    const float* qkv_w   = (const float*)d_in[3];
    const float* qkv_b   = (const float*)d_in[4];
    const float* proj_w  = (const float*)d_in[5];
    const float* proj_b  = (const float*)d_in[6];
    float* out = (float*)d_out;

    float* hin; cudaGetSymbolAddress((void**)&hin, g_hin);
    float* qkv; cudaGetSymbolAddress((void**)&qkv, g_qkv);
    float* attn; cudaGetSymbolAddress((void**)&attn, g_attn);
    float* hbuf; cudaGetSymbolAddress((void**)&hbuf, g_h);

    // 1. GroupNorm
    groupnorm_kernel<<<Bb * GROUPS, 256>>>(x, gamma, beta, hin);

    // 2. QKV: per batch  [1536,512] @ [512,1024]
    {
        dim3 grid(HW / 64, QKV_O / 64, Bb);
        gemm64<false, false><<<grid, 256>>>(
            qkv_w, hin, qkv,
            QKV_O, HW, C, /*lda=*/C, /*ldb=*/HW,
            /*sA=*/0, /*sB=*/(long)C * HW, /*sC=*/(long)QKV_O * HW,
            1.0f, qkv_b, nullptr, 0);
    }

    // 3. Scores: S[p,jj] = s^2 * sum_c q[c,p] k[c,jj]  (TA: q stored [C,HW])
    {
        const float alpha = 1.0f / sqrtf((float)C); // (C^-1/4)^2
        dim3 grid(HW / 64, HW / 64, Bb);
        gemm64<true, false><<<grid, 256>>>(
            qkv /*q*/, qkv + (long)C * HW /*k*/, attn,
            HW, HW, C, /*lda=*/HW, /*ldb=*/HW,
            /*sA=*/(long)QKV_O * HW, /*sB=*/(long)QKV_O * HW, /*sC=*/(long)HW * HW,
            alpha, nullptr, nullptr, 0);
    }

    // 4. Segmented softmax over j (last spatial axis, 32-wide chunks)
    {
        long n_segs = (long)Bb * HW * (HW / SEG);   // 1,048,576
        softmax_seg_kernel<<<(unsigned)(n_segs / 8), 256>>>(attn);
    }

    // 5. h[c,p] = sum_jj v[c,jj] * P[p,jj]   (TB: P stored [HW(p), HW(jj)])
    {
        dim3 grid(HW / 64, C / 64, Bb);
        gemm64<false, true><<<grid, 256>>>(
            qkv + 2L * C * HW /*v*/, attn, hbuf,
            C, HW, HW, /*lda=*/HW, /*ldb=*/HW,
            /*sA=*/(long)QKV_O * HW, /*sB=*/(long)HW * HW, /*sC=*/(long)C * HW,
            1.0f, nullptr, nullptr, 0);
    }

    // 6. proj + residual: out = x + proj_w @ h + proj_b
    {
        dim3 grid(HW / 64, C / 64, Bb);
        gemm64<false, false><<<grid, 256>>>(
            proj_w, hbuf, out,
            C, HW, C, /*lda=*/C, /*ldb=*/HW,
            /*sA=*/0, /*sB=*/(long)C * HW, /*sC=*/(long)C * HW,
            1.0f, proj_b, x, /*sR=*/(long)C * HW);
    }
}

// round 12
// speedup vs baseline: 2.4655x; 2.4655x over previous
#include <cuda_runtime.h>
#include <cuda_bf16.h>
#include <cstdint>
#include <math.h>

// ---------------- problem dims ----------------
#define Bb 32
#define C 512
#define HW 1024
#define GROUPS 32
#define CPG 16
#define QKV_O 1536

// ---------------- helpers ----------------
__device__ __forceinline__ uint32_t smem_u32(const void* p) {
    uint32_t a;
    asm("{ .reg .u64 t; cvta.to.shared.u64 t, %1; cvt.u32.u64 %0, t; }" : "=r"(a) : "l"(p));
    return a;
}

__device__ __forceinline__ void cp_async16(uint32_t dst, const void* src) {
    asm volatile("cp.async.cg.shared.global [%0], [%1], 16;"
                 :: "r"(dst), "l"(__cvta_generic_to_global(src)));
}
#define CP_COMMIT() asm volatile("cp.async.commit_group;" ::: "memory")
#define CP_WAIT1()  asm volatile("cp.async.wait_group 1;" ::: "memory")
#define CP_WAIT0()  asm volatile("cp.async.wait_group 0;" ::: "memory")

#define LDSM4(r, addr)                                                        \
    asm volatile("ldmatrix.sync.aligned.m8n8.x4.shared.b16 {%0,%1,%2,%3}, [%4];" \
        : "=r"((r)[0]), "=r"((r)[1]), "=r"((r)[2]), "=r"((r)[3]) : "r"(addr))

__device__ __forceinline__ void mma16816(float* c, const uint32_t* a,
                                         uint32_t b0, uint32_t b1) {
    asm volatile("mma.sync.aligned.m16n8k16.row.col.f32.bf16.bf16.f32 "
        "{%0,%1,%2,%3}, {%4,%5,%6,%7}, {%8,%9}, {%0,%1,%2,%3};"
        : "+f"(c[0]), "+f"(c[1]), "+f"(c[2]), "+f"(c[3])
        : "r"(a[0]), "r"(a[1]), "r"(a[2]), "r"(a[3]), "r"(b0), "r"(b1));
}

__device__ __forceinline__ void split_bf16(float f, __nv_bfloat16& hi, __nv_bfloat16& lo) {
    hi = __float2bfloat16(f);
    lo = __float2bfloat16(f - __bfloat162float(hi));
}

// ---------------- device scratch (bf16 hi/lo pairs) ----------------
__device__ __nv_bfloat16 g_hin_hi[(long)Bb * HW * C];
__device__ __nv_bfloat16 g_hin_lo[(long)Bb * HW * C];
__device__ __nv_bfloat16 g_qk_hi [(long)Bb * HW * 1024];
__device__ __nv_bfloat16 g_qk_lo [(long)Bb * HW * 1024];
__device__ __nv_bfloat16 g_v_hi  [(long)Bb * C * HW];
__device__ __nv_bfloat16 g_v_lo  [(long)Bb * C * HW];
__device__ __nv_bfloat16 g_P_hi  [(long)Bb * HW * HW];
__device__ __nv_bfloat16 g_P_lo  [(long)Bb * HW * HW];
__device__ __nv_bfloat16 g_h_hi  [(long)Bb * HW * C];
__device__ __nv_bfloat16 g_h_lo  [(long)Bb * HW * C];
__device__ __nv_bfloat16 g_qw_hi [QKV_O * C];
__device__ __nv_bfloat16 g_qw_lo [QKV_O * C];
__device__ __nv_bfloat16 g_pw_hi [C * C];
__device__ __nv_bfloat16 g_pw_lo [C * C];

// ---------------- weight conversion ----------------
__global__ void convert_w(const float* __restrict__ qkv_w, const float* __restrict__ proj_w) {
    for (int i = blockIdx.x * blockDim.x + threadIdx.x; i < QKV_O * C + C * C;
         i += gridDim.x * blockDim.x) {
        if (i < QKV_O * C) {
            __nv_bfloat16 h, l; split_bf16(qkv_w[i], h, l);
            g_qw_hi[i] = h; g_qw_lo[i] = l;
        } else {
            int j = i - QKV_O * C;
            __nv_bfloat16 h, l; split_bf16(proj_w[j], h, l);
            g_pw_hi[j] = h; g_pw_lo[j] = l;
        }
    }
}

// ---------------- GroupNorm -> transposed hi/lo [b, p, c] ----------------
__global__ void groupnorm_t(const float* __restrict__ x,
                            const float* __restrict__ gamma,
                            const float* __restrict__ beta)
{
    const int b = blockIdx.x / GROUPS;
    const int g = blockIdx.x % GROUPS;
    const long base = ((long)b * C + (long)g * CPG) * HW;
    const int GSZ = CPG * HW; // 16384
    const int tid = threadIdx.x;

    float sum = 0.f, sq = 0.f;
    for (int i = tid; i < GSZ; i += 256) {
        float v = x[base + i];
        sum += v; sq += v * v;
    }
    __shared__ float s_sum[8], s_sq[8];
    for (int off = 16; off > 0; off >>= 1) {
        sum += __shfl_xor_sync(0xffffffff, sum, off);
        sq  += __shfl_xor_sync(0xffffffff, sq,  off);
    }
    if ((tid & 31) == 0) { s_sum[tid >> 5] = sum; s_sq[tid >> 5] = sq; }
    __syncthreads();
    if (tid < 32) {
        sum = (tid < 8) ? s_sum[tid] : 0.f;
        sq  = (tid < 8) ? s_sq[tid]  : 0.f;
        for (int off = 4; off > 0; off >>= 1) {
            sum += __shfl_xor_sync(0xffffffff, sum, off);
            sq  += __shfl_xor_sync(0xffffffff, sq,  off);
        }
        if (tid == 0) { s_sum[0] = sum; s_sq[0] = sq; }
    }
    __syncthreads();
    const float mean = s_sum[0] * (1.f / GSZ);
    const float var  = s_sq[0]  * (1.f / GSZ) - mean * mean;
    const float rstd = rsqrtf(var + 1e-5f);

    __shared__ float ts[CPG][129];
    for (int pc = 0; pc < 8; pc++) {
        #pragma unroll
        for (int e = 0; e < 8; e++) {
            int idx = e * 256 + tid;
            int cc = idx >> 7, pp = idx & 127;
            float v = (x[base + (long)cc * HW + pc * 128 + pp] - mean) * rstd;
            ts[cc][pp] = v * gamma[g * CPG + cc] + beta[g * CPG + cc];
        }
        __syncthreads();
        #pragma unroll
        for (int e = 0; e < 8; e++) {
            int idx = e * 256 + tid;
            int pp = idx >> 4, cc = idx & 15;
            float f = ts[cc][pp];
            __nv_bfloat16 h, l; split_bf16(f, h, l);
            long o = ((long)b * HW + pc * 128 + pp) * C + g * CPG + cc;
            g_hin_hi[o] = h; g_hin_lo[o] = l;
        }
        __syncthreads();
    }
}

// ---------------- mma.sync GEMM: D[m,n] = alpha * sum_k A[m,k] B[n,k] ----------------
// CTA tile 128x128, BK=32, 8 warps (4m x 2n), warp tile 32x64.
// bf16 hi/lo 3-pass (hh + hl + lh) into shared fp32 accumulators.
// MODE 0: QKV  — n0<1024 -> qk hi/lo row-major (+bias); n0>=1024 -> v transposed (+bias)
// MODE 1: SOFT — alpha + per-32-col softmax -> P hi/lo
// MODE 2: HILO — plain hi/lo row-major
// MODE 3: FINAL— fp32 out + bias[m] + residual
static constexpr int TILE_B  = 128 * 80;        // 128 rows x 40 bf16 (padded) = 10240 B
static constexpr int STAGE_B = 4 * TILE_B;      // Ahi, Alo, Bhi, Blo = 40960 B
static constexpr int SMEM_DYN = 2 * STAGE_B;    // 81920 B (also covers 128x130 fp32 stage)

__device__ __forceinline__ void load_stage(uint32_t sbase, int stage,
    const __nv_bfloat16* __restrict__ Ah, const __nv_bfloat16* __restrict__ Al, int lda,
    const __nv_bfloat16* __restrict__ Bh, const __nv_bfloat16* __restrict__ Bl, int ldb,
    int kc0, int tid)
{
    const int tile = tid >> 6;    // 0..3
    const int u    = tid & 63;
    const __nv_bfloat16* sp;
    int ld;
    if      (tile == 0) { sp = Ah; ld = lda; }
    else if (tile == 1) { sp = Al; ld = lda; }
    else if (tile == 2) { sp = Bh; ld = ldb; }
    else                { sp = Bl; ld = ldb; }
    sp += kc0;
    uint32_t tb = sbase + stage * STAGE_B + tile * TILE_B;
    #pragma unroll
    for (int j = 0; j < 8; j++) {
        int cid = u + 64 * j;          // 0..511
        int row = cid >> 2, c16 = cid & 3;
        cp_async16(tb + row * 80 + c16 * 16, sp + (long)row * ld + c16 * 8);
    }
}

__device__ __forceinline__ void compute_stage(uint32_t sbase, int stage,
                                              int wm, int wn, int lane,
                                              float acc[2][8][4])
{
    const uint32_t st = sbase + stage * STAGE_B;
    const int lrow = lane & 15;
    const int lc16 = lane >> 4;
    #pragma unroll
    for (int kk = 0; kk < 2; kk++) {
        const int kb = kk * 32 + lc16 * 16;
        uint32_t ah[2][4], al[2][4];
        #pragma unroll
        for (int mi = 0; mi < 2; mi++) {
            uint32_t r = (uint32_t)(wm * 32 + mi * 16 + lrow) * 80 + kb;
            LDSM4(ah[mi], st + 0 * TILE_B + r);
            LDSM4(al[mi], st + 1 * TILE_B + r);
        }
        uint32_t bh[4][4], bl[4][4];
        #pragma unroll
        for (int ng = 0; ng < 4; ng++) {
            uint32_t r = (uint32_t)(wn * 64 + ng * 16 + lrow) * 80 + kb;
            LDSM4(bh[ng], st + 2 * TILE_B + r);
            LDSM4(bl[ng], st + 3 * TILE_B + r);
        }
        #pragma unroll
        for (int mi = 0; mi < 2; mi++)
            #pragma unroll
            for (int ng = 0; ng < 4; ng++) {
                float* c0 = acc[mi][ng * 2 + 0];
                float* c1 = acc[mi][ng * 2 + 1];
                mma16816(c0, ah[mi], bh[ng][0], bh[ng][2]);
                mma16816(c1, ah[mi], bh[ng][1], bh[ng][3]);
                mma16816(c0, ah[mi], bl[ng][0], bl[ng][2]);
                mma16816(c1, ah[mi], bl[ng][1], bl[ng][3]);
                mma16816(c0, al[mi], bh[ng][0], bh[ng][2]);
                mma16816(c1, al[mi], bh[ng][1], bh[ng][3]);
            }
    }
}

template<int MODE>
__global__ void __launch_bounds__(256, 1)
gemm_mma(const __nv_bfloat16* __restrict__ Ahi, const __nv_bfloat16* __restrict__ Alo,
         long sA, int lda,
         const __nv_bfloat16* __restrict__ Bhi, const __nv_bfloat16* __restrict__ Blo,
         long sB, int ldb,
         int K, float alpha,
         __nv_bfloat16* __restrict__ Ohi, __nv_bfloat16* __restrict__ Olo, long sO, int ldo,
         __nv_bfloat16* __restrict__ Vhi, __nv_bfloat16* __restrict__ Vlo, long sV, int ldv,
         float* __restrict__ Of, long sOf, int ldof,
         const float* __restrict__ bias,
         const float* __restrict__ resid, long sR, int ldr)
{
    extern __shared__ char smraw[];
    const uint32_t sbase = smem_u32(smraw);

    const int tid  = threadIdx.x;
    const int lane = tid & 31;
    const int wid  = tid >> 5;
    const int wm   = wid & 3;       // 4 m-warps
    const int wn   = wid >> 2;      // 2 n-warps
    const int m0   = blockIdx.y * 128;
    const int n0   = blockIdx.x * 128;
    const int z    = blockIdx.z;

    const __nv_bfloat16* Ah = Ahi + (long)z * sA + (long)m0 * lda;
    const __nv_bfloat16* Al = Alo + (long)z * sA + (long)m0 * lda;
    const __nv_bfloat16* Bh = Bhi + (long)z * sB + (long)n0 * ldb;
    const __nv_bfloat16* Bl = Blo + (long)z * sB + (long)n0 * ldb;

    const int NC = K >> 5;          // BK = 32

    load_stage(sbase, 0, Ah, Al, lda, Bh, Bl, ldb, 0, tid);
    CP_COMMIT();
    if (NC > 1) {
        load_stage(sbase, 1, Ah, Al, lda, Bh, Bl, ldb, 32, tid);
        CP_COMMIT();
    }

    float acc[2][8][4];
    #pragma unroll
    for (int mi = 0; mi < 2; mi++)
        #pragma unroll
        for (int t = 0; t < 8; t++)
            #pragma unroll
            for (int q = 0; q < 4; q++) acc[mi][t][q] = 0.f;

    for (int ki = 0; ki < NC; ki++) {
        if (ki == NC - 1) CP_WAIT0(); else CP_WAIT1();
        __syncthreads();
        compute_stage(sbase, ki & 1, wm, wn, lane, acc);
        __syncthreads();
        if (ki + 2 < NC) {
            load_stage(sbase, ki & 1, Ah, Al, lda, Bh, Bl, ldb, (ki + 2) * 32, tid);
            CP_COMMIT();
        }
    }

    // ---------------- epilogue ----------------
    const int g  = lane >> 2;
    const int tg = lane & 3;
    const int mb = m0 + wm * 32;
    const int nb = n0 + wn * 64;

    if (MODE == 1) {
        // segmented softmax over 32-col blocks (2 segments per warp), in-register
        #pragma unroll
        for (int mi = 0; mi < 2; mi++)
            #pragma unroll
            for (int h = 0; h < 2; h++)
                #pragma unroll
                for (int s = 0; s < 2; s++) {
                    float v[8];
                    #pragma unroll
                    for (int j = 0; j < 8; j++)
                        v[j] = acc[mi][s * 4 + (j >> 1)][h * 2 + (j & 1)] * alpha;
                    float mx = v[0];
                    #pragma unroll
                    for (int j = 1; j < 8; j++) mx = fmaxf(mx, v[j]);
                    mx = fmaxf(mx, __shfl_xor_sync(0xffffffff, mx, 1));
                    mx = fmaxf(mx, __shfl_xor_sync(0xffffffff, mx, 2));
                    float sm = 0.f;
                    #pragma unroll
                    for (int j = 0; j < 8; j++) { v[j] = __expf(v[j] - mx); sm += v[j]; }
                    sm += __shfl_xor_sync(0xffffffff, sm, 1);
                    sm += __shfl_xor_sync(0xffffffff, sm, 2);
                    float inv = 1.f / sm;
                    #pragma unroll
                    for (int j = 0; j < 8; j++)
                        acc[mi][s * 4 + (j >> 1)][h * 2 + (j & 1)] = v[j] * inv;
                }
    }

    if (MODE == 0 && n0 >= 1024) {
        // v block: stage fp32 to SMEM, transpose-store hi/lo [c][p]
        float* stg = (float*)smraw;   // 128 x 130
        #pragma unroll
        for (int mi = 0; mi < 2; mi++)
            #pragma unroll
            for (int t = 0; t < 8; t++) {
                int nl = wn * 64 + t * 8 + tg * 2;
                #pragma unroll
                for (int h = 0; h < 2; h++) {
                    int ml = wm * 32 + mi * 16 + g + h * 8;
                    stg[ml * 130 + nl]     = acc[mi][t][h * 2 + 0] + bias[n0 + nl];
                    stg[ml * 130 + nl + 1] = acc[mi][t][h * 2 + 1] + bias[n0 + nl + 1];
                }
            }
        __syncthreads();
        #pragma unroll
        for (int it = 0; it < 4; it++) {
            int task = tid + 256 * it;
            int cl = task & 127;
            int p0 = (task >> 7) * 16;
            int c = n0 - 1024 + cl;
            union { __nv_bfloat16 h[16]; uint4 u[2]; } ph, pl;
            #pragma unroll
            for (int i = 0; i < 16; i++)
                split_bf16(stg[(p0 + i) * 130 + cl], ph.h[i], pl.h[i]);
            uint4* dh = (uint4*)(Vhi + (long)z * sV + (long)c * ldv + m0 + p0);
            uint4* dl = (uint4*)(Vlo + (long)z * sV + (long)c * ldv + m0 + p0);
            dh[0] = ph.u[0]; dh[1] = ph.u[1];
            dl[0] = pl.u[0]; dl[1] = pl.u[1];
        }
        return;
    }

    if (MODE == 3) {
        // fp32 out + bias[m] + residual, direct from registers
        #pragma unroll
        for (int mi = 0; mi < 2; mi++)
            #pragma unroll
            for (int h = 0; h < 2; h++) {
                int m = mb + mi * 16 + g + h * 8;
                float bm = bias[m];
                #pragma unroll
                for (int t = 0; t < 8; t++) {
                    int n = nb + t * 8 + tg * 2;
                    float2 r = *(const float2*)&resid[(long)z * sR + (long)m * ldr + n];
                    float2 o;
                    o.x = acc[mi][t][h * 2 + 0] + bm + r.x;
                    o.y = acc[mi][t][h * 2 + 1] + bm + r.y;
                    *(float2*)&Of[(long)z * sOf + (long)m * ldof + n] = o;
                }
            }
        return;
    }

    // hi/lo row-major store (MODE 0 qk part, MODE 1 post-softmax, MODE 2)
    #pragma unroll
    for (int mi = 0; mi < 2; mi++)
        #pragma unroll
        for (int h = 0; h < 2; h++) {
            int m = mb + mi * 16 + g + h * 8;
            #pragma unroll
            for (int t = 0; t < 8; t++) {
                int n = nb + t * 8 + tg * 2;
                float f0 = acc[mi][t][h * 2 + 0];
                float f1 = acc[mi][t][h * 2 + 1];
                if (MODE == 2) { f0 *= alpha; f1 *= alpha; }
                if (MODE == 0) { f0 += bias[n]; f1 += bias[n + 1]; }
                __nv_bfloat16 h0, l0, h1, l1;
                split_bf16(f0, h0, l0);
                split_bf16(f1, h1, l1);
                __nv_bfloat162 vh2; vh2.x = h0; vh2.y = h1;
                __nv_bfloat162 vl2; vl2.x = l0; vl2.y = l1;
                *(__nv_bfloat162*)&Ohi[(long)z * sO + (long)m * ldo + n] = vh2;
                *(__nv_bfloat162*)&Olo[(long)z * sO + (long)m * ldo + n] = vl2;
            }
        }
}

// ---------------- launch ----------------
extern "C" void kernel_launch(void* const* d_in, const int* in_sizes, int n_in,
                              void* d_out, int out_size)
{
    const float* x      = (const float*)d_in[0];
    const float* gamma  = (const float*)d_in[1];
    const float* beta   = (const float*)d_in[2];
    const float* qkv_w  = (const float*)d_in[3];
    const float* qkv_b  = (const float*)d_in[4];
    const float* proj_w = (const float*)d_in[5];
    const float* proj_b = (const float*)d_in[6];
    float* out = (float*)d_out;

    __nv_bfloat16 *hinh, *hinl, *qkh, *qkl, *vh, *vl, *Ph, *Pl, *hh, *hl, *qwh, *qwl, *pwh, *pwl;
    cudaGetSymbolAddress((void**)&hinh, g_hin_hi); cudaGetSymbolAddress((void**)&hinl, g_hin_lo);
    cudaGetSymbolAddress((void**)&qkh,  g_qk_hi);  cudaGetSymbolAddress((void**)&qkl,  g_qk_lo);
    cudaGetSymbolAddress((void**)&vh,   g_v_hi);   cudaGetSymbolAddress((void**)&vl,   g_v_lo);
    cudaGetSymbolAddress((void**)&Ph,   g_P_hi);   cudaGetSymbolAddress((void**)&Pl,   g_P_lo);
    cudaGetSymbolAddress((void**)&hh,   g_h_hi);   cudaGetSymbolAddress((void**)&hl,   g_h_lo);
    cudaGetSymbolAddress((void**)&qwh,  g_qw_hi);  cudaGetSymbolAddress((void**)&qwl,  g_qw_lo);
    cudaGetSymbolAddress((void**)&pwh,  g_pw_hi);  cudaGetSymbolAddress((void**)&pwl,  g_pw_lo);

    cudaFuncSetAttribute(gemm_mma<0>, cudaFuncAttributeMaxDynamicSharedMemorySize, SMEM_DYN);
    cudaFuncSetAttribute(gemm_mma<1>, cudaFuncAttributeMaxDynamicSharedMemorySize, SMEM_DYN);
    cudaFuncSetAttribute(gemm_mma<2>, cudaFuncAttributeMaxDynamicSharedMemorySize, SMEM_DYN);
    cudaFuncSetAttribute(gemm_mma<3>, cudaFuncAttributeMaxDynamicSharedMemorySize, SMEM_DYN);

    // 0. weights -> hi/lo
    convert_w<<<512, 256>>>(qkv_w, proj_w);

    // 1. GroupNorm -> hin_t [b, p, c] hi/lo
    groupnorm_t<<<Bb * GROUPS, 256>>>(x, gamma, beta);

    // 2. QKV: D[p, o] = hin_t[p,:] . qkv_w[o,:]  (M=1024, N=1536, K=512)
    gemm_mma<0><<<dim3(12, 8, Bb), 256, SMEM_DYN>>>(
        hinh, hinl, (long)HW * C, C,
        qwh, qwl, 0L, C,
        C, 1.0f,
        qkh, qkl, (long)HW * 1024, 1024,
        vh, vl, (long)C * HW, HW,
        nullptr, 0L, 0,
        qkv_b, nullptr, 0L, 0);

    // 3. Scores + fused segmented softmax: S[p,j] = alpha * q[p,:].k[j,:]
    gemm_mma<1><<<dim3(8, 8, Bb), 256, SMEM_DYN>>>(
        qkh, qkl, (long)HW * 1024, 1024,
        qkh + 512, qkl + 512, (long)HW * 1024, 1024,
        C, 1.0f / sqrtf((float)C),
        Ph, Pl, (long)HW * HW, HW,
        nullptr, nullptr, 0L, 0,
        nullptr, 0L, 0,
        nullptr, nullptr, 0L, 0);

    // 4. PV: h_t[p, c] = P[p,:] . v[c,:]  (M=1024, N=512, K=1024)
    gemm_mma<2><<<dim3(4, 8, Bb), 256, SMEM_DYN>>>(
        Ph, Pl, (long)HW * HW, HW,
        vh, vl, (long)C * HW, HW,
        HW, 1.0f,
        hh, hl, (long)HW * C, C,
        nullptr, nullptr, 0L, 0,
        nullptr, 0L, 0,
        nullptr, nullptr, 0L, 0);

    // 5. proj + bias + residual: out[o, p] = proj_w[o,:] . h_t[p,:] + b[o] + x[o,p]
    gemm_mma<3><<<dim3(8, 4, Bb), 256, SMEM_DYN>>>(
        pwh, pwl, 0L, C,
        hh, hl, (long)HW * C, C,
        C, 1.0f,
        nullptr, nullptr, 0L, 0,
        nullptr, nullptr, 0L, 0,
        out, (long)C * HW, HW,
        proj_b, x, (long)C * HW, HW);
}

// round 14
// speedup vs baseline: 2.5538x; 1.0358x over previous
#include <cuda_runtime.h>
#include <cuda_bf16.h>
#include <cstdint>
#include <math.h>

// ---------------- problem dims ----------------
#define Bb 32
#define C 512
#define HW 1024
#define GROUPS 32
#define CPG 16
#define QKV_O 1536

// ---------------- helpers ----------------
__device__ __forceinline__ uint32_t smem_u32(const void* p) {
    uint32_t a;
    asm("{ .reg .u64 t; cvta.to.shared.u64 t, %1; cvt.u32.u64 %0, t; }" : "=r"(a) : "l"(p));
    return a;
}

__device__ __forceinline__ void cp_async16(uint32_t dst, const void* src) {
    asm volatile("cp.async.cg.shared.global [%0], [%1], 16;"
                 :: "r"(dst), "l"(__cvta_generic_to_global(src)));
}
#define CP_COMMIT() asm volatile("cp.async.commit_group;" ::: "memory")
#define CP_WAIT1()  asm volatile("cp.async.wait_group 1;" ::: "memory")
#define CP_WAIT0()  asm volatile("cp.async.wait_group 0;" ::: "memory")

#define LDSM4(r, addr)                                                        \
    asm volatile("ldmatrix.sync.aligned.m8n8.x4.shared.b16 {%0,%1,%2,%3}, [%4];" \
        : "=r"((r)[0]), "=r"((r)[1]), "=r"((r)[2]), "=r"((r)[3]) : "r"(addr))

__device__ __forceinline__ void mma16816(float* c, const uint32_t* a,
                                         uint32_t b0, uint32_t b1) {
    asm volatile("mma.sync.aligned.m16n8k16.row.col.f32.bf16.bf16.f32 "
        "{%0,%1,%2,%3}, {%4,%5,%6,%7}, {%8,%9}, {%0,%1,%2,%3};"
        : "+f"(c[0]), "+f"(c[1]), "+f"(c[2]), "+f"(c[3])
        : "r"(a[0]), "r"(a[1]), "r"(a[2]), "r"(a[3]), "r"(b0), "r"(b1));
}

__device__ __forceinline__ void split_bf16(float f, __nv_bfloat16& hi, __nv_bfloat16& lo) {
    hi = __float2bfloat16(f);
    lo = __float2bfloat16(f - __bfloat162float(hi));
}

// ---------------- device scratch (bf16 hi/lo pairs) ----------------
__device__ __nv_bfloat16 g_hin_hi[(long)Bb * HW * C];
__device__ __nv_bfloat16 g_hin_lo[(long)Bb * HW * C];
__device__ __nv_bfloat16 g_qk_hi [(long)Bb * HW * 1024];
__device__ __nv_bfloat16 g_qk_lo [(long)Bb * HW * 1024];
__device__ __nv_bfloat16 g_v_hi  [(long)Bb * C * HW];
__device__ __nv_bfloat16 g_v_lo  [(long)Bb * C * HW];
__device__ __nv_bfloat16 g_P_hi  [(long)Bb * HW * HW];
__device__ __nv_bfloat16 g_P_lo  [(long)Bb * HW * HW];
__device__ __nv_bfloat16 g_h_hi  [(long)Bb * HW * C];
__device__ __nv_bfloat16 g_h_lo  [(long)Bb * HW * C];
__device__ __nv_bfloat16 g_qw_hi [QKV_O * C];
__device__ __nv_bfloat16 g_qw_lo [QKV_O * C];
__device__ __nv_bfloat16 g_pw_hi [C * C];
__device__ __nv_bfloat16 g_pw_lo [C * C];

// ---------------- weight conversion ----------------
__global__ void convert_w(const float* __restrict__ qkv_w, const float* __restrict__ proj_w) {
    for (int i = blockIdx.x * blockDim.x + threadIdx.x; i < QKV_O * C + C * C;
         i += gridDim.x * blockDim.x) {
        if (i < QKV_O * C) {
            __nv_bfloat16 h, l; split_bf16(qkv_w[i], h, l);
            g_qw_hi[i] = h; g_qw_lo[i] = l;
        } else {
            int j = i - QKV_O * C;
            __nv_bfloat16 h, l; split_bf16(proj_w[j], h, l);
            g_pw_hi[j] = h; g_pw_lo[j] = l;
        }
    }
}

// ---------------- GroupNorm -> transposed hi/lo [b, p, c] ----------------
__global__ void groupnorm_t(const float* __restrict__ x,
                            const float* __restrict__ gamma,
                            const float* __restrict__ beta)
{
    const int b = blockIdx.x / GROUPS;
    const int g = blockIdx.x % GROUPS;
    const long base = ((long)b * C + (long)g * CPG) * HW;
    const int GSZ = CPG * HW; // 16384
    const int tid = threadIdx.x;

    float sum = 0.f, sq = 0.f;
    for (int i = tid; i < GSZ; i += 256) {
        float v = x[base + i];
        sum += v; sq += v * v;
    }
    __shared__ float s_sum[8], s_sq[8];
    for (int off = 16; off > 0; off >>= 1) {
        sum += __shfl_xor_sync(0xffffffff, sum, off);
        sq  += __shfl_xor_sync(0xffffffff, sq,  off);
    }
    if ((tid & 31) == 0) { s_sum[tid >> 5] = sum; s_sq[tid >> 5] = sq; }
    __syncthreads();
    if (tid < 32) {
        sum = (tid < 8) ? s_sum[tid] : 0.f;
        sq  = (tid < 8) ? s_sq[tid]  : 0.f;
        for (int off = 4; off > 0; off >>= 1) {
            sum += __shfl_xor_sync(0xffffffff, sum, off);
            sq  += __shfl_xor_sync(0xffffffff, sq,  off);
        }
        if (tid == 0) { s_sum[0] = sum; s_sq[0] = sq; }
    }
    __syncthreads();
    const float mean = s_sum[0] * (1.f / GSZ);
    const float var  = s_sq[0]  * (1.f / GSZ) - mean * mean;
    const float rstd = rsqrtf(var + 1e-5f);

    __shared__ float ts[CPG][129];
    for (int pc = 0; pc < 8; pc++) {
        #pragma unroll
        for (int e = 0; e < 8; e++) {
            int idx = e * 256 + tid;
            int cc = idx >> 7, pp = idx & 127;
            float v = (x[base + (long)cc * HW + pc * 128 + pp] - mean) * rstd;
            ts[cc][pp] = v * gamma[g * CPG + cc] + beta[g * CPG + cc];
        }
        __syncthreads();
        #pragma unroll
        for (int e = 0; e < 8; e++) {
            int idx = e * 256 + tid;
            int pp = idx >> 4, cc = idx & 15;
            float f = ts[cc][pp];
            __nv_bfloat16 h, l; split_bf16(f, h, l);
            long o = ((long)b * HW + pc * 128 + pp) * C + g * CPG + cc;
            g_hin_hi[o] = h; g_hin_lo[o] = l;
        }
        __syncthreads();
    }
}

// ---------------- mma.sync GEMM: D[m,n] = alpha * sum_k A[m,k] B[n,k] ----------------
// CTA tile 128x128, BK=32, 4 warps (2m x 2n), warp tile 64x64.
// bf16 hi/lo 3-pass (hh + hl + lh) into shared fp32 accumulators.
// MODE 0: QKV  — n0<1024 -> qk hi/lo row-major (+bias); n0>=1024 -> v transposed (+bias)
// MODE 1: SOFT — alpha + per-32-col softmax -> P hi/lo
// MODE 2: HILO — plain hi/lo row-major
// MODE 3: FINAL— fp32 out + bias[m] + residual
static constexpr int TILE_B  = 128 * 80;        // 128 rows x 40 bf16 (padded) = 10240 B
static constexpr int STAGE_B = 4 * TILE_B;      // Ahi, Alo, Bhi, Blo = 40960 B
static constexpr int SMEM_DYN = 2 * STAGE_B;    // 81920 B (also covers 128x130 fp32 stage)

__device__ __forceinline__ void load_stage(uint32_t sbase, int stage,
    const __nv_bfloat16* __restrict__ Ah, const __nv_bfloat16* __restrict__ Al, int lda,
    const __nv_bfloat16* __restrict__ Bh, const __nv_bfloat16* __restrict__ Bl, int ldb,
    int kc0, int tid)
{
    const int tile = tid >> 5;    // 0..3 (one warp per tile)
    const int u    = tid & 31;
    const __nv_bfloat16* sp;
    int ld;
    if      (tile == 0) { sp = Ah; ld = lda; }
    else if (tile == 1) { sp = Al; ld = lda; }
    else if (tile == 2) { sp = Bh; ld = ldb; }
    else                { sp = Bl; ld = ldb; }
    sp += kc0;
    uint32_t tb = sbase + stage * STAGE_B + tile * TILE_B;
    #pragma unroll
    for (int j = 0; j < 16; j++) {
        int cid = u + 32 * j;          // 0..511
        int row = cid >> 2, c16 = cid & 3;
        cp_async16(tb + row * 80 + c16 * 16, sp + (long)row * ld + c16 * 8);
    }
}

__device__ __forceinline__ void compute_stage(uint32_t st,
                                              int wm, int wn, int lane,
                                              float acc[4][8][4])
{
    const int lrow = lane & 15;
    const int lc16 = lane >> 4;
    #pragma unroll
    for (int kk = 0; kk < 2; kk++) {
        const int kb = kk * 32 + lc16 * 16;
        uint32_t ah[4][4], al[4][4];
        #pragma unroll
        for (int mi = 0; mi < 4; mi++) {
            uint32_t r = (uint32_t)(wm * 64 + mi * 16 + lrow) * 80 + kb;
            LDSM4(ah[mi], st + 0 * TILE_B + r);
            LDSM4(al[mi], st + 1 * TILE_B + r);
        }
        #pragma unroll
        for (int ng = 0; ng < 4; ng++) {
            uint32_t bh[4], bl[4];
            uint32_t r = (uint32_t)(wn * 64 + ng * 16 + lrow) * 80 + kb;
            LDSM4(bh, st + 2 * TILE_B + r);
            LDSM4(bl, st + 3 * TILE_B + r);
            #pragma unroll
            for (int mi = 0; mi < 4; mi++) {
                float* c0 = acc[mi][ng * 2 + 0];
                float* c1 = acc[mi][ng * 2 + 1];
                mma16816(c0, ah[mi], bh[0], bh[2]);
                mma16816(c1, ah[mi], bh[1], bh[3]);
                mma16816(c0, ah[mi], bl[0], bl[2]);
                mma16816(c1, ah[mi], bl[1], bl[3]);
                mma16816(c0, al[mi], bh[0], bh[2]);
                mma16816(c1, al[mi], bh[1], bh[3]);
            }
        }
    }
}

template<int MODE>
__global__ void __launch_bounds__(128, 2)
gemm_mma(const __nv_bfloat16* __restrict__ Ahi, const __nv_bfloat16* __restrict__ Alo,
         long sA, int lda,
         const __nv_bfloat16* __restrict__ Bhi, const __nv_bfloat16* __restrict__ Blo,
         long sB, int ldb,
         int K, float alpha,
         __nv_bfloat16* __restrict__ Ohi, __nv_bfloat16* __restrict__ Olo, long sO, int ldo,
         __nv_bfloat16* __restrict__ Vhi, __nv_bfloat16* __restrict__ Vlo, long sV, int ldv,
         float* __restrict__ Of, long sOf, int ldof,
         const float* __restrict__ bias,
         const float* __restrict__ resid, long sR, int ldr)
{
    extern __shared__ char smraw[];
    const uint32_t sbase = smem_u32(smraw);

    const int tid  = threadIdx.x;
    const int lane = tid & 31;
    const int wid  = tid >> 5;
    const int wm   = wid & 1;       // 2 m-warps
    const int wn   = wid >> 1;      // 2 n-warps
    const int m0   = blockIdx.y * 128;
    const int n0   = blockIdx.x * 128;
    const int z    = blockIdx.z;

    const __nv_bfloat16* Ah = Ahi + (long)z * sA + (long)m0 * lda;
    const __nv_bfloat16* Al = Alo + (long)z * sA + (long)m0 * lda;
    const __nv_bfloat16* Bh = Bhi + (long)z * sB + (long)n0 * ldb;
    const __nv_bfloat16* Bl = Blo + (long)z * sB + (long)n0 * ldb;

    const int NC = K >> 5;          // BK = 32

    load_stage(sbase, 0, Ah, Al, lda, Bh, Bl, ldb, 0, tid);
    CP_COMMIT();
    if (NC > 1) {
        load_stage(sbase, 1, Ah, Al, lda, Bh, Bl, ldb, 32, tid);
        CP_COMMIT();
    }

    float acc[4][8][4];
    #pragma unroll
    for (int mi = 0; mi < 4; mi++)
        #pragma unroll
        for (int t = 0; t < 8; t++)
            #pragma unroll
            for (int q = 0; q < 4; q++) acc[mi][t][q] = 0.f;

    for (int ki = 0; ki < NC; ki++) {
        if (ki == NC - 1) CP_WAIT0(); else CP_WAIT1();
        __syncthreads();
        compute_stage(sbase + (ki & 1) * STAGE_B, wm, wn, lane, acc);
        __syncthreads();
        if (ki + 2 < NC) {
            load_stage(sbase, ki & 1, Ah, Al, lda, Bh, Bl, ldb, (ki + 2) * 32, tid);
            CP_COMMIT();
        }
    }

    // ---------------- epilogue ----------------
    const int g  = lane >> 2;
    const int tg = lane & 3;
    const int mb = m0 + wm * 64;
    const int nb = n0 + wn * 64;

    if (MODE == 1) {
        // segmented softmax over 32-col blocks (2 segments per warp), in-register
        #pragma unroll
        for (int mi = 0; mi < 4; mi++)
            #pragma unroll
            for (int h = 0; h < 2; h++)
                #pragma unroll
                for (int s = 0; s < 2; s++) {
                    float v[8];
                    #pragma unroll
                    for (int j = 0; j < 8; j++)
                        v[j] = acc[mi][s * 4 + (j >> 1)][h * 2 + (j & 1)] * alpha;
                    float mx = v[0];
                    #pragma unroll
                    for (int j = 1; j < 8; j++) mx = fmaxf(mx, v[j]);
                    mx = fmaxf(mx, __shfl_xor_sync(0xffffffff, mx, 1));
                    mx = fmaxf(mx, __shfl_xor_sync(0xffffffff, mx, 2));
                    float sm = 0.f;
                    #pragma unroll
                    for (int j = 0; j < 8; j++) { v[j] = __expf(v[j] - mx); sm += v[j]; }
                    sm += __shfl_xor_sync(0xffffffff, sm, 1);
                    sm += __shfl_xor_sync(0xffffffff, sm, 2);
                    float inv = 1.f / sm;
                    #pragma unroll
                    for (int j = 0; j < 8; j++)
                        acc[mi][s * 4 + (j >> 1)][h * 2 + (j & 1)] = v[j] * inv;
                }
    }

    if (MODE == 0 && n0 >= 1024) {
        // v block: stage fp32 to SMEM, transpose-store hi/lo [c][p]
        float* stg = (float*)smraw;   // 128 x 130
        #pragma unroll
        for (int mi = 0; mi < 4; mi++)
            #pragma unroll
            for (int t = 0; t < 8; t++) {
                int nl = wn * 64 + t * 8 + tg * 2;
                #pragma unroll
                for (int h = 0; h < 2; h++) {
                    int ml = wm * 64 + mi * 16 + g + h * 8;
                    stg[ml * 130 + nl]     = acc[mi][t][h * 2 + 0] + bias[n0 + nl];
                    stg[ml * 130 + nl + 1] = acc[mi][t][h * 2 + 1] + bias[n0 + nl + 1];
                }
            }
        __syncthreads();
        #pragma unroll
        for (int it = 0; it < 8; it++) {
            int task = tid + 128 * it;
            int cl = task & 127;
            int p0 = (task >> 7) * 16;
            int c = n0 - 1024 + cl;
            union { __nv_bfloat16 h[16]; uint4 u[2]; } ph, pl;
            #pragma unroll
            for (int i = 0; i < 16; i++)
                split_bf16(stg[(p0 + i) * 130 + cl], ph.h[i], pl.h[i]);
            uint4* dh = (uint4*)(Vhi + (long)z * sV + (long)c * ldv + m0 + p0);
            uint4* dl = (uint4*)(Vlo + (long)z * sV + (long)c * ldv + m0 + p0);
            dh[0] = ph.u[0]; dh[1] = ph.u[1];
            dl[0] = pl.u[0]; dl[1] = pl.u[1];
        }
        return;
    }

    if (MODE == 3) {
        // fp32 out + bias[m] + residual, direct from registers
        #pragma unroll
        for (int mi = 0; mi < 4; mi++)
            #pragma unroll
            for (int h = 0; h < 2; h++) {
                int m = mb + mi * 16 + g + h * 8;
                float bm = bias[m];
                #pragma unroll
                for (int t = 0; t < 8; t++) {
                    int n = nb + t * 8 + tg * 2;
                    float2 r = *(const float2*)&resid[(long)z * sR + (long)m * ldr + n];
                    float2 o;
                    o.x = acc[mi][t][h * 2 + 0] + bm + r.x;
                    o.y = acc[mi][t][h * 2 + 1] + bm + r.y;
                    *(float2*)&Of[(long)z * sOf + (long)m * ldof + n] = o;
                }
            }
        return;
    }

    // hi/lo row-major store (MODE 0 qk part, MODE 1 post-softmax, MODE 2)
    #pragma unroll
    for (int mi = 0; mi < 4; mi++)
        #pragma unroll
        for (int h = 0; h < 2; h++) {
            int m = mb + mi * 16 + g + h * 8;
            #pragma unroll
            for (int t = 0; t < 8; t++) {
                int n = nb + t * 8 + tg * 2;
                float f0 = acc[mi][t][h * 2 + 0];
                float f1 = acc[mi][t][h * 2 + 1];
                if (MODE == 2) { f0 *= alpha; f1 *= alpha; }
                if (MODE == 0) { f0 += bias[n]; f1 += bias[n + 1]; }
                __nv_bfloat16 h0, l0, h1, l1;
                split_bf16(f0, h0, l0);
                split_bf16(f1, h1, l1);
                __nv_bfloat162 vh2; vh2.x = h0; vh2.y = h1;
                __nv_bfloat162 vl2; vl2.x = l0; vl2.y = l1;
                *(__nv_bfloat162*)&Ohi[(long)z * sO + (long)m * ldo + n] = vh2;
                *(__nv_bfloat162*)&Olo[(long)z * sO + (long)m * ldo + n] = vl2;
            }
        }
}

// ---------------- launch ----------------
extern "C" void kernel_launch(void* const* d_in, const int* in_sizes, int n_in,
                              void* d_out, int out_size)
{
    const float* x      = (const float*)d_in[0];
    const float* gamma  = (const float*)d_in[1];
    const float* beta   = (const float*)d_in[2];
    const float* qkv_w  = (const float*)d_in[3];
    const float* qkv_b  = (const float*)d_in[4];
    const float* proj_w = (const float*)d_in[5];
    const float* proj_b = (const float*)d_in[6];
    float* out = (float*)d_out;

    __nv_bfloat16 *hinh, *hinl, *qkh, *qkl, *vh, *vl, *Ph, *Pl, *hh, *hl, *qwh, *qwl, *pwh, *pwl;
    cudaGetSymbolAddress((void**)&hinh, g_hin_hi); cudaGetSymbolAddress((void**)&hinl, g_hin_lo);
    cudaGetSymbolAddress((void**)&qkh,  g_qk_hi);  cudaGetSymbolAddress((void**)&qkl,  g_qk_lo);
    cudaGetSymbolAddress((void**)&vh,   g_v_hi);   cudaGetSymbolAddress((void**)&vl,   g_v_lo);
    cudaGetSymbolAddress((void**)&Ph,   g_P_hi);   cudaGetSymbolAddress((void**)&Pl,   g_P_lo);
    cudaGetSymbolAddress((void**)&hh,   g_h_hi);   cudaGetSymbolAddress((void**)&hl,   g_h_lo);
    cudaGetSymbolAddress((void**)&qwh,  g_qw_hi);  cudaGetSymbolAddress((void**)&qwl,  g_qw_lo);
    cudaGetSymbolAddress((void**)&pwh,  g_pw_hi);  cudaGetSymbolAddress((void**)&pwl,  g_pw_lo);

    cudaFuncSetAttribute(gemm_mma<0>, cudaFuncAttributeMaxDynamicSharedMemorySize, SMEM_DYN);
    cudaFuncSetAttribute(gemm_mma<1>, cudaFuncAttributeMaxDynamicSharedMemorySize, SMEM_DYN);
    cudaFuncSetAttribute(gemm_mma<2>, cudaFuncAttributeMaxDynamicSharedMemorySize, SMEM_DYN);
    cudaFuncSetAttribute(gemm_mma<3>, cudaFuncAttributeMaxDynamicSharedMemorySize, SMEM_DYN);

    // 0. weights -> hi/lo
    convert_w<<<512, 256>>>(qkv_w, proj_w);

    // 1. GroupNorm -> hin_t [b, p, c] hi/lo
    groupnorm_t<<<Bb * GROUPS, 256>>>(x, gamma, beta);

    // 2. QKV: D[p, o] = hin_t[p,:] . qkv_w[o,:]  (M=1024, N=1536, K=512)
    gemm_mma<0><<<dim3(12, 8, Bb), 128, SMEM_DYN>>>(
        hinh, hinl, (long)HW * C, C,
        qwh, qwl, 0L, C,
        C, 1.0f,
        qkh, qkl, (long)HW * 1024, 1024,
        vh, vl, (long)C * HW, HW,
        nullptr, 0L, 0,
        qkv_b, nullptr, 0L, 0);

    // 3. Scores + fused segmented softmax: S[p,j] = alpha * q[p,:].k[j,:]
    gemm_mma<1><<<dim3(8, 8, Bb), 128, SMEM_DYN>>>(
        qkh, qkl, (long)HW * 1024, 1024,
        qkh + 512, qkl + 512, (long)HW * 1024, 1024,
        C, 1.0f / sqrtf((float)C),
        Ph, Pl, (long)HW * HW, HW,
        nullptr, nullptr, 0L, 0,
        nullptr, 0L, 0,
        nullptr, nullptr, 0L, 0);

    // 4. PV: h_t[p, c] = P[p,:] . v[c,:]  (M=1024, N=512, K=1024)
    gemm_mma<2><<<dim3(4, 8, Bb), 128, SMEM_DYN>>>(
        Ph, Pl, (long)HW * HW, HW,
        vh, vl, (long)C * HW, HW,
        HW, 1.0f,
        hh, hl, (long)HW * C, C,
        nullptr, nullptr, 0L, 0,
        nullptr, 0L, 0,
        nullptr, nullptr, 0L, 0);

    // 5. proj + bias + residual: out[o, p] = proj_w[o,:] . h_t[p,:] + b[o] + x[o,p]
    gemm_mma<3><<<dim3(8, 4, Bb), 128, SMEM_DYN>>>(
        pwh, pwl, 0L, C,
        hh, hl, (long)HW * C, C,
        C, 1.0f,
        nullptr, nullptr, 0L, 0,
        nullptr, nullptr, 0L, 0,
        out, (long)C * HW, HW,
        proj_b, x, (long)C * HW, HW);
}

// round 15
// speedup vs baseline: 2.6966x; 1.0559x over previous
#include <cuda_runtime.h>
#include <cuda_bf16.h>
#include <cstdint>
#include <math.h>

// ---------------- problem dims ----------------
#define Bb 32
#define C 512
#define HW 1024
#define GROUPS 32
#define CPG 16
#define QKV_O 1536

// ---------------- helpers ----------------
__device__ __forceinline__ uint32_t smem_u32(const void* p) {
    uint32_t a;
    asm("{ .reg .u64 t; cvta.to.shared.u64 t, %1; cvt.u32.u64 %0, t; }" : "=r"(a) : "l"(p));
    return a;
}

__device__ __forceinline__ void cp_async16(uint32_t dst, const void* src) {
    asm volatile("cp.async.cg.shared.global [%0], [%1], 16;"
                 :: "r"(dst), "l"(__cvta_generic_to_global(src)));
}
#define CP_COMMIT() asm volatile("cp.async.commit_group;" ::: "memory")
#define CP_WAIT1()  asm volatile("cp.async.wait_group 1;" ::: "memory")
#define CP_WAIT0()  asm volatile("cp.async.wait_group 0;" ::: "memory")

#define LDSM4(r, addr)                                                        \
    asm volatile("ldmatrix.sync.aligned.m8n8.x4.shared.b16 {%0,%1,%2,%3}, [%4];" \
        : "=r"((r)[0]), "=r"((r)[1]), "=r"((r)[2]), "=r"((r)[3]) : "r"(addr))

__device__ __forceinline__ void mma16816(float* c, const uint32_t* a,
                                         uint32_t b0, uint32_t b1) {
    asm volatile("mma.sync.aligned.m16n8k16.row.col.f32.bf16.bf16.f32 "
        "{%0,%1,%2,%3}, {%4,%5,%6,%7}, {%8,%9}, {%0,%1,%2,%3};"
        : "+f"(c[0]), "+f"(c[1]), "+f"(c[2]), "+f"(c[3])
        : "r"(a[0]), "r"(a[1]), "r"(a[2]), "r"(a[3]), "r"(b0), "r"(b1));
}

__device__ __forceinline__ void split_bf16(float f, __nv_bfloat16& hi, __nv_bfloat16& lo) {
    hi = __float2bfloat16(f);
    lo = __float2bfloat16(f - __bfloat162float(hi));
}

// ---------------- device scratch (bf16 hi/lo pairs) ----------------
__device__ __nv_bfloat16 g_hin_hi[(long)Bb * HW * C];
__device__ __nv_bfloat16 g_hin_lo[(long)Bb * HW * C];
__device__ __nv_bfloat16 g_qk_hi [(long)Bb * HW * 1024];
__device__ __nv_bfloat16 g_qk_lo [(long)Bb * HW * 1024];
__device__ __nv_bfloat16 g_v_hi  [(long)Bb * C * HW];
__device__ __nv_bfloat16 g_v_lo  [(long)Bb * C * HW];
__device__ __nv_bfloat16 g_P_hi  [(long)Bb * HW * HW];
__device__ __nv_bfloat16 g_P_lo  [(long)Bb * HW * HW];
__device__ __nv_bfloat16 g_h_hi  [(long)Bb * HW * C];
__device__ __nv_bfloat16 g_h_lo  [(long)Bb * HW * C];
__device__ __nv_bfloat16 g_qw_hi [QKV_O * C];
__device__ __nv_bfloat16 g_qw_lo [QKV_O * C];
__device__ __nv_bfloat16 g_pw_hi [C * C];
__device__ __nv_bfloat16 g_pw_lo [C * C];

// ---------------- weight conversion ----------------
__global__ void convert_w(const float* __restrict__ qkv_w, const float* __restrict__ proj_w) {
    for (int i = blockIdx.x * blockDim.x + threadIdx.x; i < QKV_O * C + C * C;
         i += gridDim.x * blockDim.x) {
        if (i < QKV_O * C) {
            __nv_bfloat16 h, l; split_bf16(qkv_w[i], h, l);
            g_qw_hi[i] = h; g_qw_lo[i] = l;
        } else {
            int j = i - QKV_O * C;
            __nv_bfloat16 h, l; split_bf16(proj_w[j], h, l);
            g_pw_hi[j] = h; g_pw_lo[j] = l;
        }
    }
}

// ---------------- GroupNorm -> transposed hi/lo [b, p, c] ----------------
__global__ void groupnorm_t(const float* __restrict__ x,
                            const float* __restrict__ gamma,
                            const float* __restrict__ beta)
{
    const int b = blockIdx.x / GROUPS;
    const int g = blockIdx.x % GROUPS;
    const long base = ((long)b * C + (long)g * CPG) * HW;
    const int GSZ = CPG * HW; // 16384
    const int tid = threadIdx.x;

    float sum = 0.f, sq = 0.f;
    for (int i = tid; i < GSZ; i += 256) {
        float v = x[base + i];
        sum += v; sq += v * v;
    }
    __shared__ float s_sum[8], s_sq[8];
    for (int off = 16; off > 0; off >>= 1) {
        sum += __shfl_xor_sync(0xffffffff, sum, off);
        sq  += __shfl_xor_sync(0xffffffff, sq,  off);
    }
    if ((tid & 31) == 0) { s_sum[tid >> 5] = sum; s_sq[tid >> 5] = sq; }
    __syncthreads();
    if (tid < 32) {
        sum = (tid < 8) ? s_sum[tid] : 0.f;
        sq  = (tid < 8) ? s_sq[tid]  : 0.f;
        for (int off = 4; off > 0; off >>= 1) {
            sum += __shfl_xor_sync(0xffffffff, sum, off);
            sq  += __shfl_xor_sync(0xffffffff, sq,  off);
        }
        if (tid == 0) { s_sum[0] = sum; s_sq[0] = sq; }
    }
    __syncthreads();
    const float mean = s_sum[0] * (1.f / GSZ);
    const float var  = s_sq[0]  * (1.f / GSZ) - mean * mean;
    const float rstd = rsqrtf(var + 1e-5f);

    __shared__ float ts[CPG][129];
    for (int pc = 0; pc < 8; pc++) {
        #pragma unroll
        for (int e = 0; e < 8; e++) {
            int idx = e * 256 + tid;
            int cc = idx >> 7, pp = idx & 127;
            float v = (x[base + (long)cc * HW + pc * 128 + pp] - mean) * rstd;
            ts[cc][pp] = v * gamma[g * CPG + cc] + beta[g * CPG + cc];
        }
        __syncthreads();
        #pragma unroll
        for (int e = 0; e < 8; e++) {
            int idx = e * 256 + tid;
            int pp = idx >> 4, cc = idx & 15;
            float f = ts[cc][pp];
            __nv_bfloat16 h, l; split_bf16(f, h, l);
            long o = ((long)b * HW + pc * 128 + pp) * C + g * CPG + cc;
            g_hin_hi[o] = h; g_hin_lo[o] = l;
        }
        __syncthreads();
    }
}

// ---------------- mma.sync GEMM: D[m,n] = alpha * sum_k A[m,k] B[n,k] ----------------
// CTA tile 128x128, BK=32, 8 warps (4m x 2n), warp tile 32x64, 2 CTAs/SM.
// bf16 hi/lo 3-pass (hh + hl + lh), pass-major MMA order (dep distance 4).
// MODE 0: QKV  — n0<1024 -> qk hi/lo row-major (+bias); n0>=1024 -> v transposed (+bias)
// MODE 1: SOFT — alpha + per-32-col softmax -> P hi/lo
// MODE 2: HILO — plain hi/lo row-major
// MODE 3: FINAL— fp32 out + bias[m] + residual
static constexpr int TILE_B  = 128 * 80;        // 128 rows x 40 bf16 (padded) = 10240 B
static constexpr int STAGE_B = 4 * TILE_B;      // Ahi, Alo, Bhi, Blo = 40960 B
static constexpr int SMEM_DYN = 2 * STAGE_B;    // 81920 B (also covers 128x130 fp32 stage)

__device__ __forceinline__ void load_stage(uint32_t sbase, int stage,
    const __nv_bfloat16* __restrict__ Ah, const __nv_bfloat16* __restrict__ Al, int lda,
    const __nv_bfloat16* __restrict__ Bh, const __nv_bfloat16* __restrict__ Bl, int ldb,
    int kc0, int tid)
{
    const int tile = tid >> 6;    // 0..3
    const int u    = tid & 63;
    const __nv_bfloat16* sp;
    int ld;
    if      (tile == 0) { sp = Ah; ld = lda; }
    else if (tile == 1) { sp = Al; ld = lda; }
    else if (tile == 2) { sp = Bh; ld = ldb; }
    else                { sp = Bl; ld = ldb; }
    sp += kc0;
    uint32_t tb = sbase + stage * STAGE_B + tile * TILE_B;
    #pragma unroll
    for (int j = 0; j < 8; j++) {
        int cid = u + 64 * j;          // 0..511
        int row = cid >> 2, c16 = cid & 3;
        cp_async16(tb + row * 80 + c16 * 16, sp + (long)row * ld + c16 * 8);
    }
}

// pass-major MMA order: within each ng, 4 independent accumulators per pass
__device__ __forceinline__ void compute_stage(uint32_t st,
                                              uint32_t aoff0, uint32_t aoff1,
                                              uint32_t boff0, uint32_t boff1,
                                              uint32_t boff2, uint32_t boff3,
                                              float acc[2][8][4])
{
    const uint32_t bofs[4] = {boff0, boff1, boff2, boff3};
    #pragma unroll
    for (int kk = 0; kk < 2; kk++) {
        const int kb = kk * 32;
        uint32_t ah[2][4], al[2][4];
        LDSM4(ah[0], st + 0 * TILE_B + aoff0 + kb);
        LDSM4(al[0], st + 1 * TILE_B + aoff0 + kb);
        LDSM4(ah[1], st + 0 * TILE_B + aoff1 + kb);
        LDSM4(al[1], st + 1 * TILE_B + aoff1 + kb);
        #pragma unroll
        for (int ng = 0; ng < 4; ng++) {
            uint32_t bh[4], bl[4];
            LDSM4(bh, st + 2 * TILE_B + bofs[ng] + kb);
            LDSM4(bl, st + 3 * TILE_B + bofs[ng] + kb);
            float* c00 = acc[0][ng * 2 + 0];
            float* c01 = acc[0][ng * 2 + 1];
            float* c10 = acc[1][ng * 2 + 0];
            float* c11 = acc[1][ng * 2 + 1];
            // pass hh
            mma16816(c00, ah[0], bh[0], bh[2]);
            mma16816(c01, ah[0], bh[1], bh[3]);
            mma16816(c10, ah[1], bh[0], bh[2]);
            mma16816(c11, ah[1], bh[1], bh[3]);
            // pass hl
            mma16816(c00, ah[0], bl[0], bl[2]);
            mma16816(c01, ah[0], bl[1], bl[3]);
            mma16816(c10, ah[1], bl[0], bl[2]);
            mma16816(c11, ah[1], bl[1], bl[3]);
            // pass lh
            mma16816(c00, al[0], bh[0], bh[2]);
            mma16816(c01, al[0], bh[1], bh[3]);
            mma16816(c10, al[1], bh[0], bh[2]);
            mma16816(c11, al[1], bh[1], bh[3]);
        }
    }
}

template<int MODE>
__global__ void __launch_bounds__(256, 2)
gemm_mma(const __nv_bfloat16* __restrict__ Ahi, const __nv_bfloat16* __restrict__ Alo,
         long sA, int lda,
         const __nv_bfloat16* __restrict__ Bhi, const __nv_bfloat16* __restrict__ Blo,
         long sB, int ldb,
         int K, float alpha,
         __nv_bfloat16* __restrict__ Ohi, __nv_bfloat16* __restrict__ Olo, long sO, int ldo,
         __nv_bfloat16* __restrict__ Vhi, __nv_bfloat16* __restrict__ Vlo, long sV, int ldv,
         float* __restrict__ Of, long sOf, int ldof,
         const float* __restrict__ bias,
         const float* __restrict__ resid, long sR, int ldr)
{
    extern __shared__ char smraw[];
    const uint32_t sbase = smem_u32(smraw);

    const int tid  = threadIdx.x;
    const int lane = tid & 31;
    const int wid  = tid >> 5;
    const int wm   = wid & 3;       // 4 m-warps
    const int wn   = wid >> 2;      // 2 n-warps
    const int m0   = blockIdx.y * 128;
    const int n0   = blockIdx.x * 128;
    const int z    = blockIdx.z;

    const __nv_bfloat16* Ah = Ahi + (long)z * sA + (long)m0 * lda;
    const __nv_bfloat16* Al = Alo + (long)z * sA + (long)m0 * lda;
    const __nv_bfloat16* Bh = Bhi + (long)z * sB + (long)n0 * ldb;
    const __nv_bfloat16* Bl = Blo + (long)z * sB + (long)n0 * ldb;

    const int NC = K >> 5;          // BK = 32; NC is even (16 or 32)

    // hoisted ldmatrix offsets (row*80 + k16sel*16)
    const int lrow = lane & 15;
    const int lc16 = lane >> 4;
    const uint32_t aoff0 = (uint32_t)(wm * 32 +  0 + lrow) * 80 + lc16 * 16;
    const uint32_t aoff1 = (uint32_t)(wm * 32 + 16 + lrow) * 80 + lc16 * 16;
    const uint32_t boff0 = (uint32_t)(wn * 64 +  0 + lrow) * 80 + lc16 * 16;
    const uint32_t boff1 = (uint32_t)(wn * 64 + 16 + lrow) * 80 + lc16 * 16;
    const uint32_t boff2 = (uint32_t)(wn * 64 + 32 + lrow) * 80 + lc16 * 16;
    const uint32_t boff3 = (uint32_t)(wn * 64 + 48 + lrow) * 80 + lc16 * 16;

    load_stage(sbase, 0, Ah, Al, lda, Bh, Bl, ldb, 0, tid);
    CP_COMMIT();
    load_stage(sbase, 1, Ah, Al, lda, Bh, Bl, ldb, 32, tid);
    CP_COMMIT();

    float acc[2][8][4];
    #pragma unroll
    for (int mi = 0; mi < 2; mi++)
        #pragma unroll
        for (int t = 0; t < 8; t++)
            #pragma unroll
            for (int q = 0; q < 4; q++) acc[mi][t][q] = 0.f;

    for (int ki = 0; ki < NC; ki += 2) {
        // ---- even iter: buffer 0 ----
        CP_WAIT1();
        __syncthreads();
        compute_stage(sbase, aoff0, aoff1, boff0, boff1, boff2, boff3, acc);
        __syncthreads();
        if (ki + 2 < NC) {
            load_stage(sbase, 0, Ah, Al, lda, Bh, Bl, ldb, (ki + 2) * 32, tid);
            CP_COMMIT();
        }
        // ---- odd iter: buffer 1 ----
        if (ki + 1 == NC - 1) CP_WAIT0(); else CP_WAIT1();
        __syncthreads();
        compute_stage(sbase + STAGE_B, aoff0, aoff1, boff0, boff1, boff2, boff3, acc);
        __syncthreads();
        if (ki + 3 < NC) {
            load_stage(sbase, 1, Ah, Al, lda, Bh, Bl, ldb, (ki + 3) * 32, tid);
            CP_COMMIT();
        }
    }

    // ---------------- epilogue ----------------
    const int g  = lane >> 2;
    const int tg = lane & 3;
    const int mb = m0 + wm * 32;
    const int nb = n0 + wn * 64;

    if (MODE == 1) {
        // segmented softmax over 32-col blocks (2 segments per warp), in-register
        #pragma unroll
        for (int mi = 0; mi < 2; mi++)
            #pragma unroll
            for (int h = 0; h < 2; h++)
                #pragma unroll
                for (int s = 0; s < 2; s++) {
                    float v[8];
                    #pragma unroll
                    for (int j = 0; j < 8; j++)
                        v[j] = acc[mi][s * 4 + (j >> 1)][h * 2 + (j & 1)] * alpha;
                    float mx = v[0];
                    #pragma unroll
                    for (int j = 1; j < 8; j++) mx = fmaxf(mx, v[j]);
                    mx = fmaxf(mx, __shfl_xor_sync(0xffffffff, mx, 1));
                    mx = fmaxf(mx, __shfl_xor_sync(0xffffffff, mx, 2));
                    float sm = 0.f;
                    #pragma unroll
                    for (int j = 0; j < 8; j++) { v[j] = __expf(v[j] - mx); sm += v[j]; }
                    sm += __shfl_xor_sync(0xffffffff, sm, 1);
                    sm += __shfl_xor_sync(0xffffffff, sm, 2);
                    float inv = 1.f / sm;
                    #pragma unroll
                    for (int j = 0; j < 8; j++)
                        acc[mi][s * 4 + (j >> 1)][h * 2 + (j & 1)] = v[j] * inv;
                }
    }

    if (MODE == 0 && n0 >= 1024) {
        // v block: stage fp32 to SMEM, transpose-store hi/lo [c][p]
        float* stg = (float*)smraw;   // 128 x 130
        #pragma unroll
        for (int mi = 0; mi < 2; mi++)
            #pragma unroll
            for (int t = 0; t < 8; t++) {
                int nl = wn * 64 + t * 8 + tg * 2;
                #pragma unroll
                for (int h = 0; h < 2; h++) {
                    int ml = wm * 32 + mi * 16 + g + h * 8;
                    stg[ml * 130 + nl]     = acc[mi][t][h * 2 + 0] + bias[n0 + nl];
                    stg[ml * 130 + nl + 1] = acc[mi][t][h * 2 + 1] + bias[n0 + nl + 1];
                }
            }
        __syncthreads();
        #pragma unroll
        for (int it = 0; it < 4; it++) {
            int task = tid + 256 * it;
            int cl = task & 127;
            int p0 = (task >> 7) * 16;
            int c = n0 - 1024 + cl;
            union { __nv_bfloat16 h[16]; uint4 u[2]; } ph, pl;
            #pragma unroll
            for (int i = 0; i < 16; i++)
                split_bf16(stg[(p0 + i) * 130 + cl], ph.h[i], pl.h[i]);
            uint4* dh = (uint4*)(Vhi + (long)z * sV + (long)c * ldv + m0 + p0);
            uint4* dl = (uint4*)(Vlo + (long)z * sV + (long)c * ldv + m0 + p0);
            dh[0] = ph.u[0]; dh[1] = ph.u[1];
            dl[0] = pl.u[0]; dl[1] = pl.u[1];
        }
        return;
    }

    if (MODE == 3) {
        // fp32 out + bias[m] + residual, direct from registers
        #pragma unroll
        for (int mi = 0; mi < 2; mi++)
            #pragma unroll
            for (int h = 0; h < 2; h++) {
                int m = mb + mi * 16 + g + h * 8;
                float bm = bias[m];
                #pragma unroll
                for (int t = 0; t < 8; t++) {
                    int n = nb + t * 8 + tg * 2;
                    float2 r = *(const float2*)&resid[(long)z * sR + (long)m * ldr + n];
                    float2 o;
                    o.x = acc[mi][t][h * 2 + 0] + bm + r.x;
                    o.y = acc[mi][t][h * 2 + 1] + bm + r.y;
                    *(float2*)&Of[(long)z * sOf + (long)m * ldof + n] = o;
                }
            }
        return;
    }

    // hi/lo row-major store (MODE 0 qk part, MODE 1 post-softmax, MODE 2)
    #pragma unroll
    for (int mi = 0; mi < 2; mi++)
        #pragma unroll
        for (int h = 0; h < 2; h++) {
            int m = mb + mi * 16 + g + h * 8;
            #pragma unroll
            for (int t = 0; t < 8; t++) {
                int n = nb + t * 8 + tg * 2;
                float f0 = acc[mi][t][h * 2 + 0];
                float f1 = acc[mi][t][h * 2 + 1];
                if (MODE == 2) { f0 *= alpha; f1 *= alpha; }
                if (MODE == 0) { f0 += bias[n]; f1 += bias[n + 1]; }
                __nv_bfloat16 h0, l0, h1, l1;
                split_bf16(f0, h0, l0);
                split_bf16(f1, h1, l1);
                __nv_bfloat162 vh2; vh2.x = h0; vh2.y = h1;
                __nv_bfloat162 vl2; vl2.x = l0; vl2.y = l1;
                *(__nv_bfloat162*)&Ohi[(long)z * sO + (long)m * ldo + n] = vh2;
                *(__nv_bfloat162*)&Olo[(long)z * sO + (long)m * ldo + n] = vl2;
            }
        }
}

// ---------------- launch ----------------
extern "C" void kernel_launch(void* const* d_in, const int* in_sizes, int n_in,
                              void* d_out, int out_size)
{
    const float* x      = (const float*)d_in[0];
    const float* gamma  = (const float*)d_in[1];
    const float* beta   = (const float*)d_in[2];
    const float* qkv_w  = (const float*)d_in[3];
    const float* qkv_b  = (const float*)d_in[4];
    const float* proj_w = (const float*)d_in[5];
    const float* proj_b = (const float*)d_in[6];
    float* out = (float*)d_out;

    __nv_bfloat16 *hinh, *hinl, *qkh, *qkl, *vh, *vl, *Ph, *Pl, *hh, *hl, *qwh, *qwl, *pwh, *pwl;
    cudaGetSymbolAddress((void**)&hinh, g_hin_hi); cudaGetSymbolAddress((void**)&hinl, g_hin_lo);
    cudaGetSymbolAddress((void**)&qkh,  g_qk_hi);  cudaGetSymbolAddress((void**)&qkl,  g_qk_lo);
    cudaGetSymbolAddress((void**)&vh,   g_v_hi);   cudaGetSymbolAddress((void**)&vl,   g_v_lo);
    cudaGetSymbolAddress((void**)&Ph,   g_P_hi);   cudaGetSymbolAddress((void**)&Pl,   g_P_lo);
    cudaGetSymbolAddress((void**)&hh,   g_h_hi);   cudaGetSymbolAddress((void**)&hl,   g_h_lo);
    cudaGetSymbolAddress((void**)&qwh,  g_qw_hi);  cudaGetSymbolAddress((void**)&qwl,  g_qw_lo);
    cudaGetSymbolAddress((void**)&pwh,  g_pw_hi);  cudaGetSymbolAddress((void**)&pwl,  g_pw_lo);

    cudaFuncSetAttribute(gemm_mma<0>, cudaFuncAttributeMaxDynamicSharedMemorySize, SMEM_DYN);
    cudaFuncSetAttribute(gemm_mma<1>, cudaFuncAttributeMaxDynamicSharedMemorySize, SMEM_DYN);
    cudaFuncSetAttribute(gemm_mma<2>, cudaFuncAttributeMaxDynamicSharedMemorySize, SMEM_DYN);
    cudaFuncSetAttribute(gemm_mma<3>, cudaFuncAttributeMaxDynamicSharedMemorySize, SMEM_DYN);

    // 0. weights -> hi/lo
    convert_w<<<512, 256>>>(qkv_w, proj_w);

    // 1. GroupNorm -> hin_t [b, p, c] hi/lo
    groupnorm_t<<<Bb * GROUPS, 256>>>(x, gamma, beta);

    // 2. QKV: D[p, o] = hin_t[p,:] . qkv_w[o,:]  (M=1024, N=1536, K=512)
    gemm_mma<0><<<dim3(12, 8, Bb), 256, SMEM_DYN>>>(
        hinh, hinl, (long)HW * C, C,
        qwh, qwl, 0L, C,
        C, 1.0f,
        qkh, qkl, (long)HW * 1024, 1024,
        vh, vl, (long)C * HW, HW,
        nullptr, 0L, 0,
        qkv_b, nullptr, 0L, 0);

    // 3. Scores + fused segmented softmax: S[p,j] = alpha * q[p,:].k[j,:]
    gemm_mma<1><<<dim3(8, 8, Bb), 256, SMEM_DYN>>>(
        qkh, qkl, (long)HW * 1024, 1024,
        qkh + 512, qkl + 512, (long)HW * 1024, 1024,
        C, 1.0f / sqrtf((float)C),
        Ph, Pl, (long)HW * HW, HW,
        nullptr, nullptr, 0L, 0,
        nullptr, 0L, 0,
        nullptr, nullptr, 0L, 0);

    // 4. PV: h_t[p, c] = P[p,:] . v[c,:]  (M=1024, N=512, K=1024)
    gemm_mma<2><<<dim3(4, 8, Bb), 256, SMEM_DYN>>>(
        Ph, Pl, (long)HW * HW, HW,
        vh, vl, (long)C * HW, HW,
        HW, 1.0f,
        hh, hl, (long)HW * C, C,
        nullptr, nullptr, 0L, 0,
        nullptr, 0L, 0,
        nullptr, nullptr, 0L, 0);

    // 5. proj + bias + residual: out[o, p] = proj_w[o,:] . h_t[p,:] + b[o] + x[o,p]
    gemm_mma<3><<<dim3(8, 4, Bb), 256, SMEM_DYN>>>(
        pwh, pwl, 0L, C,
        hh, hl, (long)HW * C, C,
        C, 1.0f,
        nullptr, nullptr, 0L, 0,
        nullptr, nullptr, 0L, 0,
        out, (long)C * HW, HW,
        proj_b, x, (long)C * HW, HW);
}

// round 16
// speedup vs baseline: 3.9431x; 1.4622x over previous
#include <cuda_runtime.h>
#include <cuda_fp16.h>
#include <cstdint>
#include <math.h>

// ---------------- problem dims ----------------
#define Bb 32
#define C 512
#define HW 1024
#define GROUPS 32
#define CPG 16
#define QKV_O 1536

// ---------------- helpers ----------------
__device__ __forceinline__ uint32_t smem_u32(const void* p) {
    uint32_t a;
    asm("{ .reg .u64 t; cvta.to.shared.u64 t, %1; cvt.u32.u64 %0, t; }" : "=r"(a) : "l"(p));
    return a;
}

__device__ __forceinline__ void cp_async16(uint32_t dst, const void* src) {
    asm volatile("cp.async.cg.shared.global [%0], [%1], 16;"
                 :: "r"(dst), "l"(__cvta_generic_to_global(src)));
}
#define CP_COMMIT() asm volatile("cp.async.commit_group;" ::: "memory")

#define LDSM4(r, addr)                                                        \
    asm volatile("ldmatrix.sync.aligned.m8n8.x4.shared.b16 {%0,%1,%2,%3}, [%4];" \
        : "=r"((r)[0]), "=r"((r)[1]), "=r"((r)[2]), "=r"((r)[3]) : "r"(addr))

__device__ __forceinline__ void mma16816(float* c, const uint32_t* a,
                                         uint32_t b0, uint32_t b1) {
    asm volatile("mma.sync.aligned.m16n8k16.row.col.f32.f16.f16.f32 "
        "{%0,%1,%2,%3}, {%4,%5,%6,%7}, {%8,%9}, {%0,%1,%2,%3};"
        : "+f"(c[0]), "+f"(c[1]), "+f"(c[2]), "+f"(c[3])
        : "r"(a[0]), "r"(a[1]), "r"(a[2]), "r"(a[3]), "r"(b0), "r"(b1));
}

__device__ __forceinline__ void split_h(float f, __half& hi, __half& lo) {
    hi = __float2half_rn(f);
    lo = __float2half_rn(f - __half2float(hi));
}

// ---------------- device scratch ----------------
__device__ __half g_hin_hi[(long)Bb * HW * C];
__device__ __half g_hin_lo[(long)Bb * HW * C];
__device__ __half g_qk    [(long)Bb * HW * 1024];   // q|k, fp16 single
__device__ __half g_v     [(long)Bb * C * HW];      // v transposed [c,p], fp16 single
__device__ __half g_P     [(long)Bb * HW * HW];     // softmaxed scores, fp16 single
__device__ __half g_h_hi  [(long)Bb * HW * C];
__device__ __half g_h_lo  [(long)Bb * HW * C];
__device__ __half g_qw_hi [QKV_O * C];
__device__ __half g_qw_lo [QKV_O * C];
__device__ __half g_pw_hi [C * C];
__device__ __half g_pw_lo [C * C];

// ---------------- weight conversion ----------------
__global__ void convert_w(const float* __restrict__ qkv_w, const float* __restrict__ proj_w) {
    for (int i = blockIdx.x * blockDim.x + threadIdx.x; i < QKV_O * C + C * C;
         i += gridDim.x * blockDim.x) {
        if (i < QKV_O * C) {
            __half h, l; split_h(qkv_w[i], h, l);
            g_qw_hi[i] = h; g_qw_lo[i] = l;
        } else {
            int j = i - QKV_O * C;
            __half h, l; split_h(proj_w[j], h, l);
            g_pw_hi[j] = h; g_pw_lo[j] = l;
        }
    }
}

// ---------------- GroupNorm -> transposed hi/lo [b, p, c] ----------------
__global__ void groupnorm_t(const float* __restrict__ x,
                            const float* __restrict__ gamma,
                            const float* __restrict__ beta)
{
    const int b = blockIdx.x / GROUPS;
    const int g = blockIdx.x % GROUPS;
    const long base = ((long)b * C + (long)g * CPG) * HW;
    const int GSZ = CPG * HW; // 16384
    const int tid = threadIdx.x;

    float sum = 0.f, sq = 0.f;
    for (int i = tid; i < GSZ; i += 256) {
        float v = x[base + i];
        sum += v; sq += v * v;
    }
    __shared__ float s_sum[8], s_sq[8];
    for (int off = 16; off > 0; off >>= 1) {
        sum += __shfl_xor_sync(0xffffffff, sum, off);
        sq  += __shfl_xor_sync(0xffffffff, sq,  off);
    }
    if ((tid & 31) == 0) { s_sum[tid >> 5] = sum; s_sq[tid >> 5] = sq; }
    __syncthreads();
    if (tid < 32) {
        sum = (tid < 8) ? s_sum[tid] : 0.f;
        sq  = (tid < 8) ? s_sq[tid]  : 0.f;
        for (int off = 4; off > 0; off >>= 1) {
            sum += __shfl_xor_sync(0xffffffff, sum, off);
            sq  += __shfl_xor_sync(0xffffffff, sq,  off);
        }
        if (tid == 0) { s_sum[0] = sum; s_sq[0] = sq; }
    }
    __syncthreads();
    const float mean = s_sum[0] * (1.f / GSZ);
    const float var  = s_sq[0]  * (1.f / GSZ) - mean * mean;
    const float rstd = rsqrtf(var + 1e-5f);

    __shared__ float ts[CPG][129];
    for (int pc = 0; pc < 8; pc++) {
        #pragma unroll
        for (int e = 0; e < 8; e++) {
            int idx = e * 256 + tid;
            int cc = idx >> 7, pp = idx & 127;
            float v = (x[base + (long)cc * HW + pc * 128 + pp] - mean) * rstd;
            ts[cc][pp] = v * gamma[g * CPG + cc] + beta[g * CPG + cc];
        }
        __syncthreads();
        #pragma unroll
        for (int e = 0; e < 8; e++) {
            int idx = e * 256 + tid;
            int pp = idx >> 4, cc = idx & 15;
            float f = ts[cc][pp];
            __half h, l; split_h(f, h, l);
            long o = ((long)b * HW + pc * 128 + pp) * C + g * CPG + cc;
            g_hin_hi[o] = h; g_hin_lo[o] = l;
        }
        __syncthreads();
    }
}

// ---------------- mma.sync GEMM: D[m,n] = alpha * sum_k A[m,k] B[n,k] ----------------
// CTA tile 128x128, BK=32, 8 warps (4m x 2n), warp tile 32x64, 2 CTAs/SM.
// PASSES=3: fp16 hi/lo (hh+hl+lh). PASSES=1: fp16 single.
// NS-stage cp.async pipeline, ONE __syncthreads per iteration.
// MODE 0: QKV  — n0<1024 -> qk fp16 (+bias); n0>=1024 -> v fp16 transposed (+bias)
// MODE 1: SOFT — alpha + per-32-col softmax -> P fp16
// MODE 2: HILO — hi/lo row-major out
// MODE 3: FINAL— fp32 out + bias[m] + residual
static constexpr int TILE_B   = 128 * 80;       // 128 rows x 40 half (padded) = 10240 B
static constexpr int SMEM_DYN = 81920;          // NS * STAGE_B = 81920 for both configs

template<int PASSES>
__device__ __forceinline__ void load_stage(uint32_t sbase, int stage,
    const __half* __restrict__ Ah, const __half* __restrict__ Al, int lda,
    const __half* __restrict__ Bh, const __half* __restrict__ Bl, int ldb,
    int kc0, int tid)
{
    constexpr int STG = (PASSES == 3 ? 4 : 2) * TILE_B;
    if (PASSES == 3) {
        const int tile = tid >> 6;    // 0..3
        const int u    = tid & 63;
        const __half* sp;
        int ld;
        if      (tile == 0) { sp = Ah; ld = lda; }
        else if (tile == 1) { sp = Al; ld = lda; }
        else if (tile == 2) { sp = Bh; ld = ldb; }
        else                { sp = Bl; ld = ldb; }
        sp += kc0;
        uint32_t tb = sbase + stage * STG + tile * TILE_B;
        #pragma unroll
        for (int j = 0; j < 8; j++) {
            int cid = u + 64 * j;          // 0..511
            int row = cid >> 2, c16 = cid & 3;
            cp_async16(tb + row * 80 + c16 * 16, sp + (long)row * ld + c16 * 8);
        }
    } else {
        const int tile = tid >> 7;    // 0..1 (A, B)
        const int u    = tid & 127;
        const __half* sp = tile ? Bh : Ah;
        const int ld = tile ? ldb : lda;
        sp += kc0;
        uint32_t tb = sbase + stage * STG + tile * TILE_B;
        #pragma unroll
        for (int j = 0; j < 4; j++) {
            int cid = u + 128 * j;         // 0..511
            int row = cid >> 2, c16 = cid & 3;
            cp_async16(tb + row * 80 + c16 * 16, sp + (long)row * ld + c16 * 8);
        }
    }
}

template<int PASSES>
__device__ __forceinline__ void compute_stage(uint32_t st,
                                              uint32_t aoff0, uint32_t aoff1,
                                              const uint32_t* bofs,
                                              float acc[2][8][4])
{
    constexpr int BOFF = (PASSES == 3) ? 2 * TILE_B : 1 * TILE_B;
    #pragma unroll
    for (int kk = 0; kk < 2; kk++) {
        const int kb = kk * 32;
        uint32_t ah[2][4], al[2][4];
        LDSM4(ah[0], st + aoff0 + kb);
        LDSM4(ah[1], st + aoff1 + kb);
        if (PASSES == 3) {
            LDSM4(al[0], st + TILE_B + aoff0 + kb);
            LDSM4(al[1], st + TILE_B + aoff1 + kb);
        }
        #pragma unroll
        for (int ng = 0; ng < 4; ng++) {
            uint32_t bh[4], bl[4];
            LDSM4(bh, st + BOFF + bofs[ng] + kb);
            if (PASSES == 3) LDSM4(bl, st + 3 * TILE_B + bofs[ng] + kb);
            float* c00 = acc[0][ng * 2 + 0];
            float* c01 = acc[0][ng * 2 + 1];
            float* c10 = acc[1][ng * 2 + 0];
            float* c11 = acc[1][ng * 2 + 1];
            // pass hh
            mma16816(c00, ah[0], bh[0], bh[2]);
            mma16816(c01, ah[0], bh[1], bh[3]);
            mma16816(c10, ah[1], bh[0], bh[2]);
            mma16816(c11, ah[1], bh[1], bh[3]);
            if (PASSES == 3) {
                // pass hl
                mma16816(c00, ah[0], bl[0], bl[2]);
                mma16816(c01, ah[0], bl[1], bl[3]);
                mma16816(c10, ah[1], bl[0], bl[2]);
                mma16816(c11, ah[1], bl[1], bl[3]);
                // pass lh
                mma16816(c00, al[0], bh[0], bh[2]);
                mma16816(c01, al[0], bh[1], bh[3]);
                mma16816(c10, al[1], bh[0], bh[2]);
                mma16816(c11, al[1], bh[1], bh[3]);
            }
        }
    }
}

template<int MODE, int PASSES, int NS>
__global__ void __launch_bounds__(256, 2)
gemm_mma(const __half* __restrict__ Ahi, const __half* __restrict__ Alo,
         long sA, int lda,
         const __half* __restrict__ Bhi, const __half* __restrict__ Blo,
         long sB, int ldb,
         int K, float alpha,
         __half* __restrict__ Ohi, __half* __restrict__ Olo, long sO, int ldo,
         __half* __restrict__ Vh, long sV, int ldv,
         float* __restrict__ Of, long sOf, int ldof,
         const float* __restrict__ bias,
         const float* __restrict__ resid, long sR, int ldr)
{
    extern __shared__ char smraw[];
    const uint32_t sbase = smem_u32(smraw);
    constexpr int STG = (PASSES == 3 ? 4 : 2) * TILE_B;

    const int tid  = threadIdx.x;
    const int lane = tid & 31;
    const int wid  = tid >> 5;
    const int wm   = wid & 3;       // 4 m-warps
    const int wn   = wid >> 2;      // 2 n-warps
    const int m0   = blockIdx.y * 128;
    const int n0   = blockIdx.x * 128;
    const int z    = blockIdx.z;

    const __half* Ah = Ahi + (long)z * sA + (long)m0 * lda;
    const __half* Al = Alo ? Alo + (long)z * sA + (long)m0 * lda : nullptr;
    const __half* Bh = Bhi + (long)z * sB + (long)n0 * ldb;
    const __half* Bl = Blo ? Blo + (long)z * sB + (long)n0 * ldb : nullptr;

    const int NC = K >> 5;          // BK = 32

    // hoisted ldmatrix offsets (row*80 + k16sel*16)
    const int lrow = lane & 15;
    const int lc16 = lane >> 4;
    const uint32_t aoff0 = (uint32_t)(wm * 32 +  0 + lrow) * 80 + lc16 * 16;
    const uint32_t aoff1 = (uint32_t)(wm * 32 + 16 + lrow) * 80 + lc16 * 16;
    uint32_t bofs[4];
    #pragma unroll
    for (int ng = 0; ng < 4; ng++)
        bofs[ng] = (uint32_t)(wn * 64 + ng * 16 + lrow) * 80 + lc16 * 16;

    // prologue: fill NS-1 stages
    #pragma unroll
    for (int s = 0; s < NS - 1; s++) {
        load_stage<PASSES>(sbase, s, Ah, Al, lda, Bh, Bl, ldb, s * 32, tid);
        CP_COMMIT();
    }

    float acc[2][8][4];
    #pragma unroll
    for (int mi = 0; mi < 2; mi++)
        #pragma unroll
        for (int t = 0; t < 8; t++)
            #pragma unroll
            for (int q = 0; q < 4; q++) acc[mi][t][q] = 0.f;

    for (int ki = 0; ki < NC; ki++) {
        asm volatile("cp.async.wait_group %0;" :: "n"(NS - 2) : "memory");
        __syncthreads();
        compute_stage<PASSES>(sbase + (ki % NS) * STG, aoff0, aoff1, bofs, acc);
        const int kn = ki + NS - 1;
        if (kn < NC)
            load_stage<PASSES>(sbase, kn % NS, Ah, Al, lda, Bh, Bl, ldb, kn * 32, tid);
        CP_COMMIT();
    }
    __syncthreads();   // protect SMEM reuse in epilogue

    // ---------------- epilogue ----------------
    const int g  = lane >> 2;
    const int tg = lane & 3;
    const int mb = m0 + wm * 32;
    const int nb = n0 + wn * 64;

    if (MODE == 1) {
        // segmented softmax over 32-col blocks (2 segments per warp), in-register
        #pragma unroll
        for (int mi = 0; mi < 2; mi++)
            #pragma unroll
            for (int h = 0; h < 2; h++)
                #pragma unroll
                for (int s = 0; s < 2; s++) {
                    float v[8];
                    #pragma unroll
                    for (int j = 0; j < 8; j++)
                        v[j] = acc[mi][s * 4 + (j >> 1)][h * 2 + (j & 1)] * alpha;
                    float mx = v[0];
                    #pragma unroll
                    for (int j = 1; j < 8; j++) mx = fmaxf(mx, v[j]);
                    mx = fmaxf(mx, __shfl_xor_sync(0xffffffff, mx, 1));
                    mx = fmaxf(mx, __shfl_xor_sync(0xffffffff, mx, 2));
                    float sm = 0.f;
                    #pragma unroll
                    for (int j = 0; j < 8; j++) { v[j] = __expf(v[j] - mx); sm += v[j]; }
                    sm += __shfl_xor_sync(0xffffffff, sm, 1);
                    sm += __shfl_xor_sync(0xffffffff, sm, 2);
                    float inv = 1.f / sm;
                    #pragma unroll
                    for (int j = 0; j < 8; j++)
                        acc[mi][s * 4 + (j >> 1)][h * 2 + (j & 1)] = v[j] * inv;
                }
    }

    if (MODE == 0 && n0 >= 1024) {
        // v block: stage fp32 to SMEM, transpose-store fp16 [c][p]
        float* stg = (float*)smraw;   // 128 x 130
        #pragma unroll
        for (int mi = 0; mi < 2; mi++)
            #pragma unroll
            for (int t = 0; t < 8; t++) {
                int nl = wn * 64 + t * 8 + tg * 2;
                #pragma unroll
                for (int h = 0; h < 2; h++) {
                    int ml = wm * 32 + mi * 16 + g + h * 8;
                    stg[ml * 130 + nl]     = acc[mi][t][h * 2 + 0] + bias[n0 + nl];
                    stg[ml * 130 + nl + 1] = acc[mi][t][h * 2 + 1] + bias[n0 + nl + 1];
                }
            }
        __syncthreads();
        #pragma unroll
        for (int it = 0; it < 4; it++) {
            int task = tid + 256 * it;
            int cl = task & 127;
            int p0 = (task >> 7) * 16;
            int c = n0 - 1024 + cl;
            union { __half h[16]; uint4 u[2]; } ph;
            #pragma unroll
            for (int i = 0; i < 16; i++)
                ph.h[i] = __float2half_rn(stg[(p0 + i) * 130 + cl]);
            uint4* dh = (uint4*)(Vh + (long)z * sV + (long)c * ldv + m0 + p0);
            dh[0] = ph.u[0]; dh[1] = ph.u[1];
        }
        return;
    }

    if (MODE == 3) {
        // fp32 out + bias[m] + residual, direct from registers
        #pragma unroll
        for (int mi = 0; mi < 2; mi++)
            #pragma unroll
            for (int h = 0; h < 2; h++) {
                int m = mb + mi * 16 + g + h * 8;
                float bm = bias[m];
                #pragma unroll
                for (int t = 0; t < 8; t++) {
                    int n = nb + t * 8 + tg * 2;
                    float2 r = *(const float2*)&resid[(long)z * sR + (long)m * ldr + n];
                    float2 o;
                    o.x = acc[mi][t][h * 2 + 0] + bm + r.x;
                    o.y = acc[mi][t][h * 2 + 1] + bm + r.y;
                    *(float2*)&Of[(long)z * sOf + (long)m * ldof + n] = o;
                }
            }
        return;
    }

    // row-major store: hi always, lo if provided (MODE 0 qk, MODE 1 P, MODE 2 h)
    #pragma unroll
    for (int mi = 0; mi < 2; mi++)
        #pragma unroll
        for (int h = 0; h < 2; h++) {
            int m = mb + mi * 16 + g + h * 8;
            #pragma unroll
            for (int t = 0; t < 8; t++) {
                int n = nb + t * 8 + tg * 2;
                float f0 = acc[mi][t][h * 2 + 0];
                float f1 = acc[mi][t][h * 2 + 1];
                if (MODE == 0) { f0 += bias[n]; f1 += bias[n + 1]; }
                if (Olo) {
                    __half h0, l0, h1, l1;
                    split_h(f0, h0, l0);
                    split_h(f1, h1, l1);
                    __half2 vh2; vh2.x = h0; vh2.y = h1;
                    __half2 vl2; vl2.x = l0; vl2.y = l1;
                    *(__half2*)&Ohi[(long)z * sO + (long)m * ldo + n] = vh2;
                    *(__half2*)&Olo[(long)z * sO + (long)m * ldo + n] = vl2;
                } else {
                    __half2 vh2;
                    vh2.x = __float2half_rn(f0);
                    vh2.y = __float2half_rn(f1);
                    *(__half2*)&Ohi[(long)z * sO + (long)m * ldo + n] = vh2;
                }
            }
        }
}

// ---------------- launch ----------------
extern "C" void kernel_launch(void* const* d_in, const int* in_sizes, int n_in,
                              void* d_out, int out_size)
{
    const float* x      = (const float*)d_in[0];
    const float* gamma  = (const float*)d_in[1];
    const float* beta   = (const float*)d_in[2];
    const float* qkv_w  = (const float*)d_in[3];
    const float* qkv_b  = (const float*)d_in[4];
    const float* proj_w = (const float*)d_in[5];
    const float* proj_b = (const float*)d_in[6];
    float* out = (float*)d_out;

    __half *hinh, *hinl, *qk, *v, *P, *hh, *hl, *qwh, *qwl, *pwh, *pwl;
    cudaGetSymbolAddress((void**)&hinh, g_hin_hi); cudaGetSymbolAddress((void**)&hinl, g_hin_lo);
    cudaGetSymbolAddress((void**)&qk,   g_qk);
    cudaGetSymbolAddress((void**)&v,    g_v);
    cudaGetSymbolAddress((void**)&P,    g_P);
    cudaGetSymbolAddress((void**)&hh,   g_h_hi);   cudaGetSymbolAddress((void**)&hl,   g_h_lo);
    cudaGetSymbolAddress((void**)&qwh,  g_qw_hi);  cudaGetSymbolAddress((void**)&qwl,  g_qw_lo);
    cudaGetSymbolAddress((void**)&pwh,  g_pw_hi);  cudaGetSymbolAddress((void**)&pwl,  g_pw_lo);

    cudaFuncSetAttribute((const void*)gemm_mma<0,3,2>, cudaFuncAttributeMaxDynamicSharedMemorySize, SMEM_DYN);
    cudaFuncSetAttribute((const void*)gemm_mma<1,1,4>, cudaFuncAttributeMaxDynamicSharedMemorySize, SMEM_DYN);
    cudaFuncSetAttribute((const void*)gemm_mma<2,1,4>, cudaFuncAttributeMaxDynamicSharedMemorySize, SMEM_DYN);
    cudaFuncSetAttribute((const void*)gemm_mma<3,3,2>, cudaFuncAttributeMaxDynamicSharedMemorySize, SMEM_DYN);

    // 0. weights -> hi/lo
    convert_w<<<512, 256>>>(qkv_w, proj_w);

    // 1. GroupNorm -> hin_t [b, p, c] hi/lo
    groupnorm_t<<<Bb * GROUPS, 256>>>(x, gamma, beta);

    // 2. QKV (3-pass): D[p, o] = hin_t[p,:] . qkv_w[o,:]  (M=1024, N=1536, K=512)
    gemm_mma<0,3,2><<<dim3(12, 8, Bb), 256, SMEM_DYN>>>(
        hinh, hinl, (long)HW * C, C,
        qwh, qwl, 0L, C,
        C, 1.0f,
        qk, nullptr, (long)HW * 1024, 1024,
        v, (long)C * HW, HW,
        nullptr, 0L, 0,
        qkv_b, nullptr, 0L, 0);

    // 3. Scores + fused segmented softmax (1-pass fp16)
    gemm_mma<1,1,4><<<dim3(8, 8, Bb), 256, SMEM_DYN>>>(
        qk, nullptr, (long)HW * 1024, 1024,
        qk + 512, nullptr, (long)HW * 1024, 1024,
        C, 1.0f / sqrtf((float)C),
        P, nullptr, (long)HW * HW, HW,
        nullptr, 0L, 0,
        nullptr, 0L, 0,
        nullptr, nullptr, 0L, 0);

    // 4. PV (1-pass fp16): h_t[p, c] = P[p,:] . v[c,:]  (M=1024, N=512, K=1024)
    gemm_mma<2,1,4><<<dim3(4, 8, Bb), 256, SMEM_DYN>>>(
        P, nullptr, (long)HW * HW, HW,
        v, nullptr, (long)C * HW, HW,
        HW, 1.0f,
        hh, hl, (long)HW * C, C,
        nullptr, 0L, 0,
        nullptr, 0L, 0,
        nullptr, nullptr, 0L, 0);

    // 5. proj + bias + residual (3-pass): out[o, p] = proj_w[o,:] . h_t[p,:] + b[o] + x[o,p]
    gemm_mma<3,3,2><<<dim3(8, 4, Bb), 256, SMEM_DYN>>>(
        pwh, pwl, 0L, C,
        hh, hl, (long)HW * C, C,
        C, 1.0f,
        nullptr, nullptr, 0L, 0,
        nullptr, 0L, 0,
        out, (long)C * HW, HW,
        proj_b, x, (long)C * HW, HW);
}